// round 1
// baseline (speedup 1.0000x reference)
#include <cuda_runtime.h>

// Problem constants: B=4, S=4096, HID=2048, H=16, P=256, D=128, N=16
#define NELEM 33554432u   // 4*4096*2048

__device__ float g_q[NELEM];
__device__ float g_k[NELEM];
__device__ float g_v[NELEM];
__device__ float g_pq[NELEM];
__device__ float g_pk[NELEM];
__device__ float g_pv[NELEM];
__device__ float g_ctx[NELEM];

// ---------------------------------------------------------------------------
// SGEMM: C[m,n] = sum_k A[m,k] * W[n,k] + bias[n]   (TN, both K-major)
// M = 16384 (grid.y*128), N = K = 2048. 128x128x16 tile, 8x8 per thread.
// ---------------------------------------------------------------------------
__global__ __launch_bounds__(256, 2)
void sgemm_tn(const float* __restrict__ A, const float* __restrict__ W,
              const float* __restrict__ bias, float* __restrict__ C) {
    const int K = 2048, N = 2048;
    __shared__ float As[16][132];
    __shared__ float Ws[16][132];

    const int bm = blockIdx.y * 128;
    const int bn = blockIdx.x * 128;
    const int tid = threadIdx.x;
    const int ty = tid >> 4;        // 0..15
    const int tx = tid & 15;        // 0..15
    const int lr = tid >> 2;        // 0..63
    const int lc = (tid & 3) << 2;  // 0,4,8,12

    const float* Ap = A + (size_t)(bm + lr) * K + lc;
    const float* Wp = W + (size_t)(bn + lr) * K + lc;

    float acc[8][8];
#pragma unroll
    for (int i = 0; i < 8; i++)
#pragma unroll
        for (int j = 0; j < 8; j++) acc[i][j] = 0.f;

    for (int k0 = 0; k0 < K; k0 += 16) {
        float4 a0 = *(const float4*)(Ap + k0);
        float4 a1 = *(const float4*)(Ap + k0 + (size_t)64 * K);
        float4 w0 = *(const float4*)(Wp + k0);
        float4 w1 = *(const float4*)(Wp + k0 + (size_t)64 * K);
        __syncthreads();
        As[lc + 0][lr] = a0.x; As[lc + 1][lr] = a0.y;
        As[lc + 2][lr] = a0.z; As[lc + 3][lr] = a0.w;
        As[lc + 0][lr + 64] = a1.x; As[lc + 1][lr + 64] = a1.y;
        As[lc + 2][lr + 64] = a1.z; As[lc + 3][lr + 64] = a1.w;
        Ws[lc + 0][lr] = w0.x; Ws[lc + 1][lr] = w0.y;
        Ws[lc + 2][lr] = w0.z; Ws[lc + 3][lr] = w0.w;
        Ws[lc + 0][lr + 64] = w1.x; Ws[lc + 1][lr + 64] = w1.y;
        Ws[lc + 2][lr + 64] = w1.z; Ws[lc + 3][lr + 64] = w1.w;
        __syncthreads();
#pragma unroll
        for (int kk = 0; kk < 16; kk++) {
            float af[8], wf[8];
            *(float4*)&af[0] = *(const float4*)&As[kk][ty * 8];
            *(float4*)&af[4] = *(const float4*)&As[kk][ty * 8 + 4];
            *(float4*)&wf[0] = *(const float4*)&Ws[kk][tx * 8];
            *(float4*)&wf[4] = *(const float4*)&Ws[kk][tx * 8 + 4];
#pragma unroll
            for (int i = 0; i < 8; i++)
#pragma unroll
                for (int j = 0; j < 8; j++) acc[i][j] += af[i] * wf[j];
        }
    }

    float bf[8];
#pragma unroll
    for (int j = 0; j < 8; j++) bf[j] = bias[bn + tx * 8 + j];
#pragma unroll
    for (int i = 0; i < 8; i++) {
        float* Cp = C + (size_t)(bm + ty * 8 + i) * N + bn + tx * 8;
        float4 r0 = make_float4(acc[i][0] + bf[0], acc[i][1] + bf[1],
                                acc[i][2] + bf[2], acc[i][3] + bf[3]);
        float4 r1 = make_float4(acc[i][4] + bf[4], acc[i][5] + bf[5],
                                acc[i][6] + bf[6], acc[i][7] + bf[7]);
        *(float4*)Cp = r0;
        *(float4*)(Cp + 4) = r1;
    }
}

// ---------------------------------------------------------------------------
// Repack: proj (B,S,H,D) -> paged (x2=b*16+head, h2=s>>8, p2=2*dim+((s>>7)&1),
// d2 = s&127). 128x128 smem transpose per (b, head, s-block of 128).
// ---------------------------------------------------------------------------
__global__ __launch_bounds__(256)
void repack3(const float* __restrict__ q, const float* __restrict__ k,
             const float* __restrict__ v, float* __restrict__ pq,
             float* __restrict__ pk, float* __restrict__ pv) {
    extern __shared__ float tile[];  // [128][129]
    const int sb = blockIdx.x;    // 0..31  -> s0 = sb*128
    const int head = blockIdx.y;  // 0..15
    const int b = blockIdx.z;     // 0..3
    const int tid = threadIdx.x, warp = tid >> 5, lane = tid & 31;
    const int s0 = sb << 7;
    const int n = s0 >> 8;
    const int par = (s0 >> 7) & 1;
    const size_t sbase = ((size_t)(b * 4096 + s0)) * 2048 + head * 128;
    const size_t obase = (((size_t)(b * 16 + head) * 16 + n) << 15) + par * 128;

    const float* srcs[3] = {q, k, v};
    float* dsts[3] = {pq, pk, pv};
#pragma unroll
    for (int t = 0; t < 3; t++) {
        const float* src = srcs[t];
        float* dst = dsts[t];
        if (t) __syncthreads();
        for (int r = warp; r < 128; r += 8) {
            const float* s = src + sbase + (size_t)r * 2048;
#pragma unroll
            for (int c = 0; c < 4; c++)
                tile[r * 129 + lane + 32 * c] = s[lane + 32 * c];
        }
        __syncthreads();
        for (int dim = warp; dim < 128; dim += 8) {
            float* d = dst + obase + dim * 256;
#pragma unroll
            for (int c = 0; c < 4; c++)
                d[lane + 32 * c] = tile[(lane + 32 * c) * 129 + dim];
        }
    }
}

// ---------------------------------------------------------------------------
// Attention: one block per (qt in 0..3, h2 in 0..15, x2 in 0..63).
// Q tile 64x128, full-row S (64x256) in smem, exact softmax, O = P@V.
// Output scattered directly into the final pre-Wo layout.
// ---------------------------------------------------------------------------
#define SQT_SZ (128 * 65)   // 8320
#define SKV_SZ 8448         // max(128*65, 64*132)
#define SS_SZ  (64 * 264)   // 16896
#define ATTN_SMEM_FLOATS (SQT_SZ + SKV_SZ + SS_SZ)
#define ATTN_SMEM_BYTES  (ATTN_SMEM_FLOATS * 4)

__global__ __launch_bounds__(256)
void attn_kernel(const float* __restrict__ pQ, const float* __restrict__ pK,
                 const float* __restrict__ pV, float* __restrict__ ctx) {
    extern __shared__ float sm[];
    float* sQt = sm;                   // [128][65] transposed Q (d-major)
    float* sKV = sm + SQT_SZ;          // K: [128][65] / V: [64][132]
    float* sS = sm + SQT_SZ + SKV_SZ;  // [64][264]

    const float SCALE = 0.08838834764831843f;  // 128^-0.5
    const int qt = blockIdx.x, h2 = blockIdx.y, x2 = blockIdx.z;
    const int b = x2 >> 4, head = x2 & 15;
    const int tid = threadIdx.x, warp = tid >> 5, lane = tid & 31;
    const int ty = tid >> 4, tx = tid & 15;
    const size_t base = ((size_t)(x2 * 16 + h2)) << 15;  // *256*128

    // Load Q tile (rows qt*64..+63), transposed: sQt[d*65 + p]
    for (int r = warp; r < 64; r += 8) {
        const float* s = pQ + base + (size_t)(qt * 64 + r) * 128;
#pragma unroll
        for (int c = 0; c < 4; c++) {
            int d = lane + 32 * c;
            sQt[d * 65 + r] = s[d];
        }
    }

    // S = Q @ K^T * SCALE, tiled over 4 K-tiles of 64 rows
    for (int kt = 0; kt < 4; kt++) {
        __syncthreads();
        for (int r = warp; r < 64; r += 8) {
            const float* s = pK + base + (size_t)(kt * 64 + r) * 128;
#pragma unroll
            for (int c = 0; c < 4; c++) {
                int d = lane + 32 * c;
                sKV[d * 65 + r] = s[d];
            }
        }
        __syncthreads();
        float acc[4][4] = {};
#pragma unroll 4
        for (int k = 0; k < 128; k++) {
            float a[4], bb[4];
#pragma unroll
            for (int i = 0; i < 4; i++) a[i] = sQt[k * 65 + ty * 4 + i];
#pragma unroll
            for (int j = 0; j < 4; j++) bb[j] = sKV[k * 65 + tx * 4 + j];
#pragma unroll
            for (int i = 0; i < 4; i++)
#pragma unroll
                for (int j = 0; j < 4; j++) acc[i][j] += a[i] * bb[j];
        }
#pragma unroll
        for (int i = 0; i < 4; i++)
#pragma unroll
            for (int j = 0; j < 4; j++)
                sS[(ty * 4 + i) * 264 + kt * 64 + tx * 4 + j] = acc[i][j] * SCALE;
    }
    __syncthreads();

    // Exact softmax over each of 64 rows (256 cols), 1 warp per row
    for (int r = warp; r < 64; r += 8) {
        float v[8];
        float m = -3.4e38f;
#pragma unroll
        for (int c = 0; c < 8; c++) {
            v[c] = sS[r * 264 + 32 * c + lane];
            m = fmaxf(m, v[c]);
        }
#pragma unroll
        for (int o = 16; o; o >>= 1) m = fmaxf(m, __shfl_xor_sync(0xffffffffu, m, o));
        float sum = 0.f;
#pragma unroll
        for (int c = 0; c < 8; c++) {
            v[c] = __expf(v[c] - m);
            sum += v[c];
        }
#pragma unroll
        for (int o = 16; o; o >>= 1) sum += __shfl_xor_sync(0xffffffffu, sum, o);
        float inv = 1.0f / sum;
#pragma unroll
        for (int c = 0; c < 8; c++) sS[r * 264 + 32 * c + lane] = v[c] * inv;
    }

    // O = P @ V  (accumulate over 4 V-tiles of 64 rows)
    float o[4][8] = {};
    for (int vt = 0; vt < 4; vt++) {
        __syncthreads();
        for (int r = warp; r < 64; r += 8) {
            const float* s = pV + base + (size_t)(vt * 64 + r) * 128;
#pragma unroll
            for (int c = 0; c < 4; c++)
                sKV[r * 132 + lane + 32 * c] = s[lane + 32 * c];
        }
        __syncthreads();
#pragma unroll 2
        for (int q = 0; q < 64; q++) {
            float a[4];
#pragma unroll
            for (int i = 0; i < 4; i++) a[i] = sS[(ty * 4 + i) * 264 + vt * 64 + q];
            float4 b0 = *(const float4*)&sKV[q * 132 + tx * 8];
            float4 b1 = *(const float4*)&sKV[q * 132 + tx * 8 + 4];
#pragma unroll
            for (int i = 0; i < 4; i++) {
                o[i][0] += a[i] * b0.x; o[i][1] += a[i] * b0.y;
                o[i][2] += a[i] * b0.z; o[i][3] += a[i] * b0.w;
                o[i][4] += a[i] * b1.x; o[i][5] += a[i] * b1.y;
                o[i][6] += a[i] * b1.z; o[i][7] += a[i] * b1.w;
            }
        }
    }

    // Scatter to final pre-Wo layout: row = b*4096 + head*256 + p2, col = h2*128 + d2
#pragma unroll
    for (int i = 0; i < 4; i++) {
        int p2 = qt * 64 + ty * 4 + i;
        float* d = ctx + ((size_t)(b * 4096 + head * 256 + p2)) * 2048 + h2 * 128 + tx * 8;
        *(float4*)d = make_float4(o[i][0], o[i][1], o[i][2], o[i][3]);
        *(float4*)(d + 4) = make_float4(o[i][4], o[i][5], o[i][6], o[i][7]);
    }
}

// ---------------------------------------------------------------------------
extern "C" void kernel_launch(void* const* d_in, const int* in_sizes, int n_in,
                              void* d_out, int out_size) {
    const float* hidden = (const float*)d_in[0];
    const float* Wq = (const float*)d_in[1];
    const float* bq = (const float*)d_in[2];
    const float* Wk = (const float*)d_in[3];
    const float* bk = (const float*)d_in[4];
    const float* Wv = (const float*)d_in[5];
    const float* bv = (const float*)d_in[6];
    const float* Wo = (const float*)d_in[7];
    const float* bo = (const float*)d_in[8];
    float* out = (float*)d_out;

    float *q, *k, *v, *pq, *pk, *pv, *ctx;
    cudaGetSymbolAddress((void**)&q, g_q);
    cudaGetSymbolAddress((void**)&k, g_k);
    cudaGetSymbolAddress((void**)&v, g_v);
    cudaGetSymbolAddress((void**)&pq, g_pq);
    cudaGetSymbolAddress((void**)&pk, g_pk);
    cudaGetSymbolAddress((void**)&pv, g_pv);
    cudaGetSymbolAddress((void**)&ctx, g_ctx);

    cudaFuncSetAttribute(repack3, cudaFuncAttributeMaxDynamicSharedMemorySize,
                         128 * 129 * 4);
    cudaFuncSetAttribute(attn_kernel, cudaFuncAttributeMaxDynamicSharedMemorySize,
                         ATTN_SMEM_BYTES);

    dim3 gg(16, 128);  // N/128, M/128
    sgemm_tn<<<gg, 256>>>(hidden, Wq, bq, q);
    sgemm_tn<<<gg, 256>>>(hidden, Wk, bk, k);
    sgemm_tn<<<gg, 256>>>(hidden, Wv, bv, v);
    repack3<<<dim3(32, 16, 4), 256, 128 * 129 * 4>>>(q, k, v, pq, pk, pv);
    attn_kernel<<<dim3(4, 16, 64), 256, ATTN_SMEM_BYTES>>>(pq, pk, pv, ctx);
    sgemm_tn<<<gg, 256>>>(ctx, Wo, bo, out);
}

// round 3
// speedup vs baseline: 2.2862x; 2.2862x over previous
#include <cuda_runtime.h>
#include <cuda_bf16.h>
#include <cstdint>

// Problem constants: B=4, S=4096, HID=2048, H=16, P=256, D=128, N=16
#define NELEM 33554432u   // 4*4096*2048
#define KBIG 6144
#define NCHUNK 96         // KBIG / 64
#define MDIM 16384
#define NDIM 2048

__device__ float g_q[NELEM];
__device__ float g_k[NELEM];
__device__ float g_v[NELEM];
__device__ float g_pq[NELEM];
__device__ float g_pk[NELEM];
__device__ float g_pv[NELEM];
__device__ float g_ctx[NELEM];

__device__ __nv_bfloat16 g_hbig[(size_t)MDIM * KBIG];   // hidden: [hi,hi,lo]
__device__ __nv_bfloat16 g_cbig[(size_t)MDIM * KBIG];   // ctx:    [hi,hi,lo]
__device__ __nv_bfloat16 g_wq[(size_t)NDIM * KBIG];     // W: [hi,lo,hi]
__device__ __nv_bfloat16 g_wk[(size_t)NDIM * KBIG];
__device__ __nv_bfloat16 g_wv[(size_t)NDIM * KBIG];
__device__ __nv_bfloat16 g_wo[(size_t)NDIM * KBIG];

// ---------------------------------------------------------------------------
// helpers
// ---------------------------------------------------------------------------
__device__ __forceinline__ uint32_t smem_u32(const void* p) {
    uint32_t a;
    asm("{ .reg .u64 t; cvta.to.shared.u64 t, %1; cvt.u32.u64 %0, t; }"
        : "=r"(a) : "l"(p));
    return a;
}
__device__ __forceinline__ void cp16(uint32_t sa, const void* g) {
    asm volatile("cp.async.cg.shared.global [%0], [%1], 16;" :: "r"(sa), "l"(g));
}
#define CP_COMMIT() asm volatile("cp.async.commit_group;" ::: "memory")

__device__ __forceinline__ void ldsm4(uint32_t* r, uint32_t addr) {
    asm volatile("ldmatrix.sync.aligned.m8n8.x4.shared.b16 {%0,%1,%2,%3}, [%4];"
                 : "=r"(r[0]), "=r"(r[1]), "=r"(r[2]), "=r"(r[3]) : "r"(addr));
}
__device__ __forceinline__ void mma16816(float* c, const uint32_t* a,
                                         const uint32_t* b) {
    asm volatile(
        "mma.sync.aligned.m16n8k16.row.col.f32.bf16.bf16.f32 "
        "{%0,%1,%2,%3}, {%4,%5,%6,%7}, {%8,%9}, {%0,%1,%2,%3};"
        : "+f"(c[0]), "+f"(c[1]), "+f"(c[2]), "+f"(c[3])
        : "r"(a[0]), "r"(a[1]), "r"(a[2]), "r"(a[3]), "r"(b[0]), "r"(b[1]));
}
__device__ __forceinline__ uint32_t swz(uint32_t o) { return o ^ ((o >> 3) & 0x70); }

// ---------------------------------------------------------------------------
// fp32 -> split-bf16 buffers. mode=0 (activation): [hi, hi, lo]
// mode=1 (weight): [hi, lo, hi].
// ---------------------------------------------------------------------------
__global__ __launch_bounds__(256)
void make_big(const float* __restrict__ src, __nv_bfloat16* __restrict__ dst, int mode) {
    size_t t = (size_t)blockIdx.x * 256 + threadIdx.x;
    size_t row = t >> 9;
    int col = (int)(t & 511) << 2;
    float4 x = *(const float4*)(src + row * 2048 + col);
    __nv_bfloat16 h[4], l[4];
    float xs[4] = {x.x, x.y, x.z, x.w};
#pragma unroll
    for (int i = 0; i < 4; i++) {
        h[i] = __float2bfloat16(xs[i]);
        l[i] = __float2bfloat16(xs[i] - __bfloat162float(h[i]));
    }
    __nv_bfloat16* d0 = dst + row * KBIG + col;
    uint32_t hp0 = *(uint32_t*)&h[0], hp1 = *(uint32_t*)&h[2];
    uint32_t lp0 = *(uint32_t*)&l[0], lp1 = *(uint32_t*)&l[2];
    ((uint32_t*)d0)[0] = hp0; ((uint32_t*)d0)[1] = hp1;
    if (mode == 0) {
        ((uint32_t*)(d0 + 2048))[0] = hp0; ((uint32_t*)(d0 + 2048))[1] = hp1;
        ((uint32_t*)(d0 + 4096))[0] = lp0; ((uint32_t*)(d0 + 4096))[1] = lp1;
    } else {
        ((uint32_t*)(d0 + 2048))[0] = lp0; ((uint32_t*)(d0 + 2048))[1] = lp1;
        ((uint32_t*)(d0 + 4096))[0] = hp0; ((uint32_t*)(d0 + 4096))[1] = hp1;
    }
}

// ---------------------------------------------------------------------------
// HMMA GEMM: C[16384,2048] = Abig[16384,6144] @ Bbig[2048,6144]^T + bias
// 128x128 block, K-chunk 64 bf16 (128B rows, SW128), 3-stage cp.async ring,
// mma.sync m16n8k16 bf16. 8 warps: warp tile 32m x 64n.
// ---------------------------------------------------------------------------
#define NSTG 3
#define STG_BYTES 32768
#define GEMM_SMEM (NSTG * STG_BYTES)

__global__ __launch_bounds__(256, 2)
void gemm_hmma(const __nv_bfloat16* __restrict__ A,
               const __nv_bfloat16* __restrict__ B,
               const float* __restrict__ bias, float* __restrict__ C) {
    extern __shared__ char dsm[];
    const uint32_t data = smem_u32(dsm);
    const int tid = threadIdx.x;
    const int wid = tid >> 5, lane = tid & 31;
    const int bn = blockIdx.x << 7, bm = blockIdx.y << 7;
    const int m_base = (wid & 3) * 32;
    const int n_base = (wid >> 2) * 64;

    // loader mapping (each thread: 8 x 16B per stage)
    const int t8 = tid >> 3;      // 0..31
    const int col16 = tid & 7;    // 0..7

    // Prologue: chunks 0..2 -> stages 0..2
#pragma unroll
    for (int c = 0; c < NSTG; c++) {
        uint32_t stg = data + c * STG_BYTES;
#pragma unroll
        for (int j = 0; j < 8; j++) {
            int idx = t8 + j * 32;
            int row = idx & 127;
            bool isB = idx >= 128;
            const __nv_bfloat16* src =
                (isB ? B + (size_t)(bn + row) * KBIG : A + (size_t)(bm + row) * KBIG)
                + c * 64 + col16 * 8;
            uint32_t off = swz((uint32_t)(row * 128 + col16 * 16));
            cp16(stg + (isB ? 16384 : 0) + off, src);
        }
        CP_COMMIT();
    }

    float acc[2][8][4];
#pragma unroll
    for (int mt = 0; mt < 2; mt++)
#pragma unroll
        for (int nt = 0; nt < 8; nt++)
#pragma unroll
            for (int r = 0; r < 4; r++) acc[mt][nt][r] = 0.f;

    // precomputed fragment rows
    const int raL = lane & 15;               // A frag row (within 16)
    const int akh = lane >> 4;               // A k-half
    const int rbL = (lane & 7) + ((lane & 16) >> 1);  // B row within 16
    const int bkh = (lane >> 3) & 1;         // B k-half

    for (int i = 0; i < NCHUNK; i++) {
        int pend = NCHUNK - 1 - i; if (pend > 2) pend = 2;
        if (pend == 2)      asm volatile("cp.async.wait_group 2;" ::: "memory");
        else if (pend == 1) asm volatile("cp.async.wait_group 1;" ::: "memory");
        else                asm volatile("cp.async.wait_group 0;" ::: "memory");
        __syncthreads();

        uint32_t sA = data + (i % 3) * STG_BYTES;
        uint32_t sB = sA + 16384;

#pragma unroll
        for (int ks = 0; ks < 4; ks++) {
            uint32_t a[2][4];
#pragma unroll
            for (int mt = 0; mt < 2; mt++) {
                int ra = m_base + mt * 16 + raL;
                uint32_t ck = (uint32_t)(ks * 2 + akh) ^ (uint32_t)(ra & 7);
                ldsm4(a[mt], sA + (uint32_t)(ra * 128) + (ck << 4));
            }
            uint32_t b[4][4];
#pragma unroll
            for (int nt2 = 0; nt2 < 4; nt2++) {
                int rb = n_base + nt2 * 16 + rbL;
                uint32_t ck = (uint32_t)(ks * 2 + bkh) ^ (uint32_t)(rb & 7);
                ldsm4(b[nt2], sB + (uint32_t)(rb * 128) + (ck << 4));
            }
#pragma unroll
            for (int mt = 0; mt < 2; mt++)
#pragma unroll
                for (int nt = 0; nt < 8; nt++)
                    mma16816(acc[mt][nt], a[mt], &b[nt >> 1][(nt & 1) * 2]);
        }
        __syncthreads();

        int nc = i + NSTG;
        if (nc < NCHUNK) {
            uint32_t stg = data + (i % 3) * STG_BYTES;
#pragma unroll
            for (int j = 0; j < 8; j++) {
                int idx = t8 + j * 32;
                int row = idx & 127;
                bool isB = idx >= 128;
                const __nv_bfloat16* src =
                    (isB ? B + (size_t)(bn + row) * KBIG : A + (size_t)(bm + row) * KBIG)
                    + nc * 64 + col16 * 8;
                uint32_t off = swz((uint32_t)(row * 128 + col16 * 16));
                cp16(stg + (isB ? 16384 : 0) + off, src);
            }
            CP_COMMIT();
        }
    }

    // Epilogue: bias + store
#pragma unroll
    for (int mt = 0; mt < 2; mt++) {
        int r0 = bm + m_base + mt * 16 + (lane >> 2);
#pragma unroll
        for (int nt = 0; nt < 8; nt++) {
            int col = bn + n_base + nt * 8 + (lane & 3) * 2;
            float b0 = bias[col], b1 = bias[col + 1];
            float* p0 = C + (size_t)r0 * NDIM + col;
            float* p1 = p0 + (size_t)8 * NDIM;
            float2 v0 = make_float2(acc[mt][nt][0] + b0, acc[mt][nt][1] + b1);
            float2 v1 = make_float2(acc[mt][nt][2] + b0, acc[mt][nt][3] + b1);
            *(float2*)p0 = v0;
            *(float2*)p1 = v1;
        }
    }
}

// ---------------------------------------------------------------------------
// Repack: proj (B,S,H,D) -> paged layout
// ---------------------------------------------------------------------------
__global__ __launch_bounds__(256)
void repack3(const float* __restrict__ q, const float* __restrict__ k,
             const float* __restrict__ v, float* __restrict__ pq,
             float* __restrict__ pk, float* __restrict__ pv) {
    extern __shared__ float tile[];  // [128][129]
    const int sb = blockIdx.x;
    const int head = blockIdx.y;
    const int b = blockIdx.z;
    const int tid = threadIdx.x, warp = tid >> 5, lane = tid & 31;
    const int s0 = sb << 7;
    const int n = s0 >> 8;
    const int par = (s0 >> 7) & 1;
    const size_t sbase = ((size_t)(b * 4096 + s0)) * 2048 + head * 128;
    const size_t obase = (((size_t)(b * 16 + head) * 16 + n) << 15) + par * 128;

    const float* srcs[3] = {q, k, v};
    float* dsts[3] = {pq, pk, pv};
#pragma unroll
    for (int t = 0; t < 3; t++) {
        const float* src = srcs[t];
        float* dst = dsts[t];
        if (t) __syncthreads();
        for (int r = warp; r < 128; r += 8) {
            const float* s = src + sbase + (size_t)r * 2048;
#pragma unroll
            for (int c = 0; c < 4; c++)
                tile[r * 129 + lane + 32 * c] = s[lane + 32 * c];
        }
        __syncthreads();
        for (int dim = warp; dim < 128; dim += 8) {
            float* d = dst + obase + dim * 256;
#pragma unroll
            for (int c = 0; c < 4; c++)
                d[lane + 32 * c] = tile[(lane + 32 * c) * 129 + dim];
        }
    }
}

// ---------------------------------------------------------------------------
// Attention (fp32, smem-resident S)
// ---------------------------------------------------------------------------
#define SQT_SZ (128 * 65)
#define SKV_SZ 8448
#define SS_SZ  (64 * 264)
#define ATTN_SMEM_BYTES ((SQT_SZ + SKV_SZ + SS_SZ) * 4)

__global__ __launch_bounds__(256)
void attn_kernel(const float* __restrict__ pQ, const float* __restrict__ pK,
                 const float* __restrict__ pV, float* __restrict__ ctx) {
    extern __shared__ float sm[];
    float* sQt = sm;
    float* sKV = sm + SQT_SZ;
    float* sS = sm + SQT_SZ + SKV_SZ;

    const float SCALE = 0.08838834764831843f;
    const int qt = blockIdx.x, h2 = blockIdx.y, x2 = blockIdx.z;
    const int b = x2 >> 4, head = x2 & 15;
    const int tid = threadIdx.x, warp = tid >> 5, lane = tid & 31;
    const int ty = tid >> 4, tx = tid & 15;
    const size_t base = ((size_t)(x2 * 16 + h2)) << 15;

    for (int r = warp; r < 64; r += 8) {
        const float* s = pQ + base + (size_t)(qt * 64 + r) * 128;
#pragma unroll
        for (int c = 0; c < 4; c++) {
            int d = lane + 32 * c;
            sQt[d * 65 + r] = s[d];
        }
    }

    for (int kt = 0; kt < 4; kt++) {
        __syncthreads();
        for (int r = warp; r < 64; r += 8) {
            const float* s = pK + base + (size_t)(kt * 64 + r) * 128;
#pragma unroll
            for (int c = 0; c < 4; c++) {
                int d = lane + 32 * c;
                sKV[d * 65 + r] = s[d];
            }
        }
        __syncthreads();
        float acc[4][4] = {};
#pragma unroll 4
        for (int k = 0; k < 128; k++) {
            float a[4], bb[4];
#pragma unroll
            for (int i = 0; i < 4; i++) a[i] = sQt[k * 65 + ty * 4 + i];
#pragma unroll
            for (int j = 0; j < 4; j++) bb[j] = sKV[k * 65 + tx * 4 + j];
#pragma unroll
            for (int i = 0; i < 4; i++)
#pragma unroll
                for (int j = 0; j < 4; j++) acc[i][j] += a[i] * bb[j];
        }
#pragma unroll
        for (int i = 0; i < 4; i++)
#pragma unroll
            for (int j = 0; j < 4; j++)
                sS[(ty * 4 + i) * 264 + kt * 64 + tx * 4 + j] = acc[i][j] * SCALE;
    }
    __syncthreads();

    for (int r = warp; r < 64; r += 8) {
        float v[8];
        float m = -3.4e38f;
#pragma unroll
        for (int c = 0; c < 8; c++) {
            v[c] = sS[r * 264 + 32 * c + lane];
            m = fmaxf(m, v[c]);
        }
#pragma unroll
        for (int o = 16; o; o >>= 1) m = fmaxf(m, __shfl_xor_sync(0xffffffffu, m, o));
        float sum = 0.f;
#pragma unroll
        for (int c = 0; c < 8; c++) {
            v[c] = __expf(v[c] - m);
            sum += v[c];
        }
#pragma unroll
        for (int o = 16; o; o >>= 1) sum += __shfl_xor_sync(0xffffffffu, sum, o);
        float inv = 1.0f / sum;
#pragma unroll
        for (int c = 0; c < 8; c++) sS[r * 264 + 32 * c + lane] = v[c] * inv;
    }

    float o[4][8] = {};
    for (int vt = 0; vt < 4; vt++) {
        __syncthreads();
        for (int r = warp; r < 64; r += 8) {
            const float* s = pV + base + (size_t)(vt * 64 + r) * 128;
#pragma unroll
            for (int c = 0; c < 4; c++)
                sKV[r * 132 + lane + 32 * c] = s[lane + 32 * c];
        }
        __syncthreads();
#pragma unroll 2
        for (int q = 0; q < 64; q++) {
            float a[4];
#pragma unroll
            for (int i = 0; i < 4; i++) a[i] = sS[(ty * 4 + i) * 264 + vt * 64 + q];
            float4 b0 = *(const float4*)&sKV[q * 132 + tx * 8];
            float4 b1 = *(const float4*)&sKV[q * 132 + tx * 8 + 4];
#pragma unroll
            for (int i = 0; i < 4; i++) {
                o[i][0] += a[i] * b0.x; o[i][1] += a[i] * b0.y;
                o[i][2] += a[i] * b0.z; o[i][3] += a[i] * b0.w;
                o[i][4] += a[i] * b1.x; o[i][5] += a[i] * b1.y;
                o[i][6] += a[i] * b1.z; o[i][7] += a[i] * b1.w;
            }
        }
    }

#pragma unroll
    for (int i = 0; i < 4; i++) {
        int p2 = qt * 64 + ty * 4 + i;
        float* d = ctx + ((size_t)(b * 4096 + head * 256 + p2)) * 2048 + h2 * 128 + tx * 8;
        *(float4*)d = make_float4(o[i][0], o[i][1], o[i][2], o[i][3]);
        *(float4*)(d + 4) = make_float4(o[i][4], o[i][5], o[i][6], o[i][7]);
    }
}

// ---------------------------------------------------------------------------
extern "C" void kernel_launch(void* const* d_in, const int* in_sizes, int n_in,
                              void* d_out, int out_size) {
    const float* hidden = (const float*)d_in[0];
    const float* Wq = (const float*)d_in[1];
    const float* bq = (const float*)d_in[2];
    const float* Wk = (const float*)d_in[3];
    const float* bk = (const float*)d_in[4];
    const float* Wv = (const float*)d_in[5];
    const float* bv = (const float*)d_in[6];
    const float* Wo = (const float*)d_in[7];
    const float* bo = (const float*)d_in[8];
    float* out = (float*)d_out;

    float *q, *k, *v, *pq, *pk, *pv, *ctx;
    __nv_bfloat16 *hbig, *cbig, *wq, *wk, *wv, *wo;
    cudaGetSymbolAddress((void**)&q, g_q);
    cudaGetSymbolAddress((void**)&k, g_k);
    cudaGetSymbolAddress((void**)&v, g_v);
    cudaGetSymbolAddress((void**)&pq, g_pq);
    cudaGetSymbolAddress((void**)&pk, g_pk);
    cudaGetSymbolAddress((void**)&pv, g_pv);
    cudaGetSymbolAddress((void**)&ctx, g_ctx);
    cudaGetSymbolAddress((void**)&hbig, g_hbig);
    cudaGetSymbolAddress((void**)&cbig, g_cbig);
    cudaGetSymbolAddress((void**)&wq, g_wq);
    cudaGetSymbolAddress((void**)&wk, g_wk);
    cudaGetSymbolAddress((void**)&wv, g_wv);
    cudaGetSymbolAddress((void**)&wo, g_wo);

    cudaFuncSetAttribute(repack3, cudaFuncAttributeMaxDynamicSharedMemorySize,
                         128 * 129 * 4);
    cudaFuncSetAttribute(attn_kernel, cudaFuncAttributeMaxDynamicSharedMemorySize,
                         ATTN_SMEM_BYTES);
    cudaFuncSetAttribute(gemm_hmma, cudaFuncAttributeMaxDynamicSharedMemorySize,
                         GEMM_SMEM);

    make_big<<<4096, 256>>>(Wq, wq, 1);
    make_big<<<4096, 256>>>(Wk, wk, 1);
    make_big<<<4096, 256>>>(Wv, wv, 1);
    make_big<<<4096, 256>>>(Wo, wo, 1);
    make_big<<<32768, 256>>>(hidden, hbig, 0);

    dim3 gg(16, 128);  // N/128, M/128
    gemm_hmma<<<gg, 256, GEMM_SMEM>>>(hbig, wq, bq, q);
    gemm_hmma<<<gg, 256, GEMM_SMEM>>>(hbig, wk, bk, k);
    gemm_hmma<<<gg, 256, GEMM_SMEM>>>(hbig, wv, bv, v);
    repack3<<<dim3(32, 16, 4), 256, 128 * 129 * 4>>>(q, k, v, pq, pk, pv);
    attn_kernel<<<dim3(4, 16, 64), 256, ATTN_SMEM_BYTES>>>(pq, pk, pv, ctx);
    make_big<<<32768, 256>>>(ctx, cbig, 0);
    gemm_hmma<<<gg, 256, GEMM_SMEM>>>(cbig, wo, bo, out);
}

// round 4
// speedup vs baseline: 2.3100x; 1.0104x over previous
#include <cuda_runtime.h>
#include <cuda_bf16.h>
#include <cstdint>

// Problem constants: B=4, S=4096, HID=2048, H=16, P=256, D=128, N=16
#define NELEM 33554432u   // 4*4096*2048
#define KBIG 6144
#define NCHUNK 96         // KBIG / 64
#define MDIM 16384
#define NDIM 2048

__device__ float g_pq[NELEM];
__device__ float g_pk[NELEM];
__device__ float g_pv[NELEM];

__device__ __nv_bfloat16 g_hbig[(size_t)MDIM * KBIG];   // hidden: [hi,hi,lo]
__device__ __nv_bfloat16 g_cbig[(size_t)MDIM * KBIG];   // ctx:    [hi,hi,lo]
__device__ __nv_bfloat16 g_wq[(size_t)NDIM * KBIG];     // W: [hi,lo,hi]
__device__ __nv_bfloat16 g_wk[(size_t)NDIM * KBIG];
__device__ __nv_bfloat16 g_wv[(size_t)NDIM * KBIG];
__device__ __nv_bfloat16 g_wo[(size_t)NDIM * KBIG];

// ---------------------------------------------------------------------------
// helpers
// ---------------------------------------------------------------------------
__device__ __forceinline__ uint32_t smem_u32(const void* p) {
    uint32_t a;
    asm("{ .reg .u64 t; cvta.to.shared.u64 t, %1; cvt.u32.u64 %0, t; }"
        : "=r"(a) : "l"(p));
    return a;
}
__device__ __forceinline__ void cp16(uint32_t sa, const void* g) {
    asm volatile("cp.async.cg.shared.global [%0], [%1], 16;" :: "r"(sa), "l"(g));
}
#define CP_COMMIT() asm volatile("cp.async.commit_group;" ::: "memory")

__device__ __forceinline__ void ldsm4(uint32_t* r, uint32_t addr) {
    asm volatile("ldmatrix.sync.aligned.m8n8.x4.shared.b16 {%0,%1,%2,%3}, [%4];"
                 : "=r"(r[0]), "=r"(r[1]), "=r"(r[2]), "=r"(r[3]) : "r"(addr));
}
__device__ __forceinline__ void mma16816(float* c, const uint32_t* a,
                                         const uint32_t* b) {
    asm volatile(
        "mma.sync.aligned.m16n8k16.row.col.f32.bf16.bf16.f32 "
        "{%0,%1,%2,%3}, {%4,%5,%6,%7}, {%8,%9}, {%0,%1,%2,%3};"
        : "+f"(c[0]), "+f"(c[1]), "+f"(c[2]), "+f"(c[3])
        : "r"(a[0]), "r"(a[1]), "r"(a[2]), "r"(a[3]), "r"(b[0]), "r"(b[1]));
}
__device__ __forceinline__ uint32_t swz(uint32_t o) { return o ^ ((o >> 3) & 0x70); }

// ---------------------------------------------------------------------------
// fp32 -> split-bf16 buffers. mode=0 (activation): [hi, hi, lo]
// mode=1 (weight): [hi, lo, hi].
// ---------------------------------------------------------------------------
__global__ __launch_bounds__(256)
void make_big(const float* __restrict__ src, __nv_bfloat16* __restrict__ dst, int mode) {
    size_t t = (size_t)blockIdx.x * 256 + threadIdx.x;
    size_t row = t >> 9;
    int col = (int)(t & 511) << 2;
    float4 x = *(const float4*)(src + row * 2048 + col);
    __nv_bfloat16 h[4], l[4];
    float xs[4] = {x.x, x.y, x.z, x.w};
#pragma unroll
    for (int i = 0; i < 4; i++) {
        h[i] = __float2bfloat16(xs[i]);
        l[i] = __float2bfloat16(xs[i] - __bfloat162float(h[i]));
    }
    __nv_bfloat16* d0 = dst + row * KBIG + col;
    uint32_t hp0 = *(uint32_t*)&h[0], hp1 = *(uint32_t*)&h[2];
    uint32_t lp0 = *(uint32_t*)&l[0], lp1 = *(uint32_t*)&l[2];
    ((uint32_t*)d0)[0] = hp0; ((uint32_t*)d0)[1] = hp1;
    if (mode == 0) {
        ((uint32_t*)(d0 + 2048))[0] = hp0; ((uint32_t*)(d0 + 2048))[1] = hp1;
        ((uint32_t*)(d0 + 4096))[0] = lp0; ((uint32_t*)(d0 + 4096))[1] = lp1;
    } else {
        ((uint32_t*)(d0 + 2048))[0] = lp0; ((uint32_t*)(d0 + 2048))[1] = lp1;
        ((uint32_t*)(d0 + 4096))[0] = hp0; ((uint32_t*)(d0 + 4096))[1] = hp1;
    }
}

// ---------------------------------------------------------------------------
// HMMA GEMM: C[16384,2048] = Abig[16384,6144] @ Bbig[2048,6144]^T + bias
// Block tile 128m x 256n, K-chunk 64 bf16 (128B rows, SW128), 3-stage
// cp.async ring. 8 warps as 2m x 4n, warp tile 64x64.
// mode 0: plain C store (row-major). mode 1: paged scatter (fused repack).
// ---------------------------------------------------------------------------
#define NSTG 3
#define STG_BYTES 49152   // A 16KB + B 32KB
#define GEMM_SMEM (NSTG * STG_BYTES)

__global__ __launch_bounds__(256, 1)
void gemm_hmma(const __nv_bfloat16* __restrict__ A,
               const __nv_bfloat16* __restrict__ B,
               const float* __restrict__ bias, float* __restrict__ C, int mode) {
    extern __shared__ char dsm[];
    const uint32_t data = smem_u32(dsm);
    const int tid = threadIdx.x;
    const int wid = tid >> 5, lane = tid & 31;
    const int bn = blockIdx.x << 8, bm = blockIdx.y << 7;
    const int m_base = (wid & 1) * 64;
    const int n_base = (wid >> 1) * 64;

    // Prologue: chunks 0..2 -> stages 0..2 (12 cp16 per thread per stage)
#pragma unroll
    for (int c = 0; c < NSTG; c++) {
        uint32_t stg = data + c * STG_BYTES;
#pragma unroll
        for (int j = 0; j < 12; j++) {
            int idx = j * 256 + tid;        // 0..3071
            int row = idx >> 3;             // 0..383
            int c16 = idx & 7;
            bool isB = row >= 128;
            int r = isB ? row - 128 : row;
            const __nv_bfloat16* src =
                (isB ? B + (size_t)(bn + r) * KBIG : A + (size_t)(bm + r) * KBIG)
                + c * 64 + c16 * 8;
            uint32_t off = swz((uint32_t)(r * 128 + c16 * 16));
            cp16(stg + (isB ? 16384 : 0) + off, src);
        }
        CP_COMMIT();
    }

    float acc[4][8][4];
#pragma unroll
    for (int mt = 0; mt < 4; mt++)
#pragma unroll
        for (int nt = 0; nt < 8; nt++)
#pragma unroll
            for (int r = 0; r < 4; r++) acc[mt][nt][r] = 0.f;

    const int raL = lane & 15;
    const int akh = lane >> 4;
    const int rbL = (lane & 7) + ((lane & 16) >> 1);
    const int bkh = (lane >> 3) & 1;

    for (int i = 0; i < NCHUNK; i++) {
        int pend = NCHUNK - 1 - i; if (pend > 2) pend = 2;
        if (pend == 2)      asm volatile("cp.async.wait_group 2;" ::: "memory");
        else if (pend == 1) asm volatile("cp.async.wait_group 1;" ::: "memory");
        else                asm volatile("cp.async.wait_group 0;" ::: "memory");
        __syncthreads();

        uint32_t sA = data + (i % 3) * STG_BYTES;
        uint32_t sB = sA + 16384;

#pragma unroll
        for (int ks = 0; ks < 4; ks++) {
            uint32_t a[4][4];
#pragma unroll
            for (int mt = 0; mt < 4; mt++) {
                int ra = m_base + mt * 16 + raL;
                uint32_t ck = (uint32_t)(ks * 2 + akh) ^ (uint32_t)(ra & 7);
                ldsm4(a[mt], sA + (uint32_t)(ra * 128) + (ck << 4));
            }
            uint32_t b[4][4];
#pragma unroll
            for (int nt2 = 0; nt2 < 4; nt2++) {
                int rb = n_base + nt2 * 16 + rbL;
                uint32_t ck = (uint32_t)(ks * 2 + bkh) ^ (uint32_t)(rb & 7);
                ldsm4(b[nt2], sB + (uint32_t)(rb * 128) + (ck << 4));
            }
#pragma unroll
            for (int mt = 0; mt < 4; mt++)
#pragma unroll
                for (int nt = 0; nt < 8; nt++)
                    mma16816(acc[mt][nt], a[mt], &b[nt >> 1][(nt & 1) * 2]);
        }
        __syncthreads();

        int nc = i + NSTG;
        if (nc < NCHUNK) {
            uint32_t stg = data + (i % 3) * STG_BYTES;
#pragma unroll
            for (int j = 0; j < 12; j++) {
                int idx = j * 256 + tid;
                int row = idx >> 3;
                int c16 = idx & 7;
                bool isB = row >= 128;
                int r = idx >= 1024 ? row - 128 : row;
                const __nv_bfloat16* src =
                    (isB ? B + (size_t)(bn + r) * KBIG : A + (size_t)(bm + r) * KBIG)
                    + nc * 64 + c16 * 8;
                uint32_t off = swz((uint32_t)(r * 128 + c16 * 16));
                cp16(stg + (isB ? 16384 : 0) + off, src);
            }
            CP_COMMIT();
        }
    }

    if (mode == 0) {
        // plain epilogue: bias + row-major store
#pragma unroll
        for (int mt = 0; mt < 4; mt++) {
            int r0 = bm + m_base + mt * 16 + (lane >> 2);
#pragma unroll
            for (int nt = 0; nt < 8; nt++) {
                int col = bn + n_base + nt * 8 + (lane & 3) * 2;
                float b0 = bias[col], b1 = bias[col + 1];
                float* p0 = C + (size_t)r0 * NDIM + col;
                float* p1 = p0 + (size_t)8 * NDIM;
                *(float2*)p0 = make_float2(acc[mt][nt][0] + b0, acc[mt][nt][1] + b1);
                *(float2*)p1 = make_float2(acc[mt][nt][2] + b0, acc[mt][nt][3] + b1);
            }
        }
        return;
    }

    // mode 1: fused repack. Tile m = 128 s-values in one (b, s-block), tile n
    // = 256 dims = 2 heads. Transposed store into paged layout.
    const int b = bm >> 12;
    const int s0 = bm & 4095;
    const int page = s0 >> 8;
    const int par = (s0 >> 7) & 1;

    // bias add into acc
#pragma unroll
    for (int mt = 0; mt < 4; mt++)
#pragma unroll
        for (int nt = 0; nt < 8; nt++) {
            int col = bn + n_base + nt * 8 + (lane & 3) * 2;
            float b0 = bias[col], b1 = bias[col + 1];
            acc[mt][nt][0] += b0; acc[mt][nt][1] += b1;
            acc[mt][nt][2] += b0; acc[mt][nt][3] += b1;
        }

    __syncthreads();  // drain mainloop smem reads before reuse
    float* smf = (float*)dsm;  // transposed tile [d2:128][s:132]

#pragma unroll 1
    for (int hh = 0; hh < 2; hh++) {
        if ((wid >> 2) == hh) {
            int cbase = n_base - hh * 128;  // 0 or 64
#pragma unroll
            for (int mt = 0; mt < 4; mt++) {
                int r = m_base + mt * 16 + (lane >> 2);
#pragma unroll
                for (int nt = 0; nt < 8; nt++) {
                    int c = cbase + nt * 8 + (lane & 3) * 2;
                    smf[c * 132 + r] = acc[mt][nt][0];
                    smf[(c + 1) * 132 + r] = acc[mt][nt][1];
                    smf[c * 132 + r + 8] = acc[mt][nt][2];
                    smf[(c + 1) * 132 + r + 8] = acc[mt][nt][3];
                }
            }
        }
        __syncthreads();
        int head = (bn >> 7) + hh;
        float* dst = C + (((size_t)((b * 16 + head) * 16 + page)) << 15) + par * 128;
        int s4 = lane * 4;
#pragma unroll
        for (int it = 0; it < 16; it++) {
            int d2 = it * 8 + wid;
            float4 v = *(const float4*)&smf[d2 * 132 + s4];
            *(float4*)(dst + d2 * 256 + s4) = v;
        }
        __syncthreads();
    }
}

// ---------------------------------------------------------------------------
// Attention (fp32, smem-resident S); epilogue writes split-bf16 cbig directly.
// ---------------------------------------------------------------------------
#define SQT_SZ (128 * 65)
#define SKV_SZ 8448
#define SS_SZ  (64 * 264)
#define ATTN_SMEM_BYTES ((SQT_SZ + SKV_SZ + SS_SZ) * 4)

__global__ __launch_bounds__(256)
void attn_kernel(const float* __restrict__ pQ, const float* __restrict__ pK,
                 const float* __restrict__ pV, __nv_bfloat16* __restrict__ cbig) {
    extern __shared__ float sm[];
    float* sQt = sm;
    float* sKV = sm + SQT_SZ;
    float* sS = sm + SQT_SZ + SKV_SZ;

    const float SCALE = 0.08838834764831843f;
    const int qt = blockIdx.x, h2 = blockIdx.y, x2 = blockIdx.z;
    const int b = x2 >> 4, head = x2 & 15;
    const int tid = threadIdx.x, warp = tid >> 5, lane = tid & 31;
    const int ty = tid >> 4, tx = tid & 15;
    const size_t base = ((size_t)(x2 * 16 + h2)) << 15;

    for (int r = warp; r < 64; r += 8) {
        const float* s = pQ + base + (size_t)(qt * 64 + r) * 128;
#pragma unroll
        for (int c = 0; c < 4; c++) {
            int d = lane + 32 * c;
            sQt[d * 65 + r] = s[d];
        }
    }

    for (int kt = 0; kt < 4; kt++) {
        __syncthreads();
        for (int r = warp; r < 64; r += 8) {
            const float* s = pK + base + (size_t)(kt * 64 + r) * 128;
#pragma unroll
            for (int c = 0; c < 4; c++) {
                int d = lane + 32 * c;
                sKV[d * 65 + r] = s[d];
            }
        }
        __syncthreads();
        float acc[4][4] = {};
#pragma unroll 4
        for (int k = 0; k < 128; k++) {
            float a[4], bb[4];
#pragma unroll
            for (int i = 0; i < 4; i++) a[i] = sQt[k * 65 + ty * 4 + i];
#pragma unroll
            for (int j = 0; j < 4; j++) bb[j] = sKV[k * 65 + tx * 4 + j];
#pragma unroll
            for (int i = 0; i < 4; i++)
#pragma unroll
                for (int j = 0; j < 4; j++) acc[i][j] += a[i] * bb[j];
        }
#pragma unroll
        for (int i = 0; i < 4; i++)
#pragma unroll
            for (int j = 0; j < 4; j++)
                sS[(ty * 4 + i) * 264 + kt * 64 + tx * 4 + j] = acc[i][j] * SCALE;
    }
    __syncthreads();

    for (int r = warp; r < 64; r += 8) {
        float v[8];
        float m = -3.4e38f;
#pragma unroll
        for (int c = 0; c < 8; c++) {
            v[c] = sS[r * 264 + 32 * c + lane];
            m = fmaxf(m, v[c]);
        }
#pragma unroll
        for (int o = 16; o; o >>= 1) m = fmaxf(m, __shfl_xor_sync(0xffffffffu, m, o));
        float sum = 0.f;
#pragma unroll
        for (int c = 0; c < 8; c++) {
            v[c] = __expf(v[c] - m);
            sum += v[c];
        }
#pragma unroll
        for (int o = 16; o; o >>= 1) sum += __shfl_xor_sync(0xffffffffu, sum, o);
        float inv = 1.0f / sum;
#pragma unroll
        for (int c = 0; c < 8; c++) sS[r * 264 + 32 * c + lane] = v[c] * inv;
    }

    float o[4][8] = {};
    for (int vt = 0; vt < 4; vt++) {
        __syncthreads();
        for (int r = warp; r < 64; r += 8) {
            const float* s = pV + base + (size_t)(vt * 64 + r) * 128;
#pragma unroll
            for (int c = 0; c < 4; c++)
                sKV[r * 132 + lane + 32 * c] = s[lane + 32 * c];
        }
        __syncthreads();
#pragma unroll 2
        for (int q = 0; q < 64; q++) {
            float a[4];
#pragma unroll
            for (int i = 0; i < 4; i++) a[i] = sS[(ty * 4 + i) * 264 + vt * 64 + q];
            float4 b0 = *(const float4*)&sKV[q * 132 + tx * 8];
            float4 b1 = *(const float4*)&sKV[q * 132 + tx * 8 + 4];
#pragma unroll
            for (int i = 0; i < 4; i++) {
                o[i][0] += a[i] * b0.x; o[i][1] += a[i] * b0.y;
                o[i][2] += a[i] * b0.z; o[i][3] += a[i] * b0.w;
                o[i][4] += a[i] * b1.x; o[i][5] += a[i] * b1.y;
                o[i][6] += a[i] * b1.z; o[i][7] += a[i] * b1.w;
            }
        }
    }

    // Epilogue: split each value into bf16 hi/lo and write cbig [hi, hi, lo]
#pragma unroll
    for (int i = 0; i < 4; i++) {
        int p2 = qt * 64 + ty * 4 + i;
        size_t row = (size_t)(b * 4096 + head * 256 + p2);
        __nv_bfloat16* d = cbig + row * KBIG + h2 * 128 + tx * 8;
        uint32_t H[4], L[4];
#pragma unroll
        for (int j = 0; j < 4; j++) {
            __nv_bfloat16 h0 = __float2bfloat16(o[i][2 * j]);
            __nv_bfloat16 h1 = __float2bfloat16(o[i][2 * j + 1]);
            __nv_bfloat16 l0 = __float2bfloat16(o[i][2 * j] - __bfloat162float(h0));
            __nv_bfloat16 l1 = __float2bfloat16(o[i][2 * j + 1] - __bfloat162float(h1));
            H[j] = (uint32_t)*(uint16_t*)&h0 | ((uint32_t)*(uint16_t*)&h1 << 16);
            L[j] = (uint32_t)*(uint16_t*)&l0 | ((uint32_t)*(uint16_t*)&l1 << 16);
        }
        uint4 Hv = make_uint4(H[0], H[1], H[2], H[3]);
        uint4 Lv = make_uint4(L[0], L[1], L[2], L[3]);
        *(uint4*)d = Hv;
        *(uint4*)(d + 2048) = Hv;
        *(uint4*)(d + 4096) = Lv;
    }
}

// ---------------------------------------------------------------------------
extern "C" void kernel_launch(void* const* d_in, const int* in_sizes, int n_in,
                              void* d_out, int out_size) {
    const float* hidden = (const float*)d_in[0];
    const float* Wq = (const float*)d_in[1];
    const float* bq = (const float*)d_in[2];
    const float* Wk = (const float*)d_in[3];
    const float* bk = (const float*)d_in[4];
    const float* Wv = (const float*)d_in[5];
    const float* bv = (const float*)d_in[6];
    const float* Wo = (const float*)d_in[7];
    const float* bo = (const float*)d_in[8];
    float* out = (float*)d_out;

    float *pq, *pk, *pv;
    __nv_bfloat16 *hbig, *cbig, *wq, *wk, *wv, *wo;
    cudaGetSymbolAddress((void**)&pq, g_pq);
    cudaGetSymbolAddress((void**)&pk, g_pk);
    cudaGetSymbolAddress((void**)&pv, g_pv);
    cudaGetSymbolAddress((void**)&hbig, g_hbig);
    cudaGetSymbolAddress((void**)&cbig, g_cbig);
    cudaGetSymbolAddress((void**)&wq, g_wq);
    cudaGetSymbolAddress((void**)&wk, g_wk);
    cudaGetSymbolAddress((void**)&wv, g_wv);
    cudaGetSymbolAddress((void**)&wo, g_wo);

    cudaFuncSetAttribute(attn_kernel, cudaFuncAttributeMaxDynamicSharedMemorySize,
                         ATTN_SMEM_BYTES);
    cudaFuncSetAttribute(gemm_hmma, cudaFuncAttributeMaxDynamicSharedMemorySize,
                         GEMM_SMEM);

    make_big<<<4096, 256>>>(Wq, wq, 1);
    make_big<<<4096, 256>>>(Wk, wk, 1);
    make_big<<<4096, 256>>>(Wv, wv, 1);
    make_big<<<4096, 256>>>(Wo, wo, 1);
    make_big<<<32768, 256>>>(hidden, hbig, 0);

    dim3 gg(8, 128);  // N/256, M/128
    gemm_hmma<<<gg, 256, GEMM_SMEM>>>(hbig, wq, bq, pq, 1);
    gemm_hmma<<<gg, 256, GEMM_SMEM>>>(hbig, wk, bk, pk, 1);
    gemm_hmma<<<gg, 256, GEMM_SMEM>>>(hbig, wv, bv, pv, 1);
    attn_kernel<<<dim3(4, 16, 64), 256, ATTN_SMEM_BYTES>>>(pq, pk, pv, cbig);
    gemm_hmma<<<gg, 256, GEMM_SMEM>>>(cbig, wo, bo, out, 0);
}

// round 5
// speedup vs baseline: 2.8057x; 1.2146x over previous
#include <cuda_runtime.h>
#include <cuda_bf16.h>
#include <cstdint>

typedef __nv_bfloat16 bf16;

// Problem constants: B=4, S=4096, HID=2048, H=16, P=256, D=128, N=16
#define NELEM 33554432u   // 4*4096*2048
#define KBIG 6144
#define NCHUNK 96         // KBIG / 64
#define MDIM 16384
#define NDIM 2048

// paged bf16 hi/lo buffers: [page=(b*16+head)*16+n][256][128]
__device__ bf16 g_qhi[NELEM];
__device__ bf16 g_qlo[NELEM];
__device__ bf16 g_khi[NELEM];
__device__ bf16 g_klo[NELEM];
__device__ bf16 g_vthi[NELEM];  // transposed: [page][d2:128][p2:256]
__device__ bf16 g_vtlo[NELEM];

__device__ bf16 g_hbig[(size_t)MDIM * KBIG];   // hidden: [hi,hi,lo]
__device__ bf16 g_cbig[(size_t)MDIM * KBIG];   // ctx:    [hi,hi,lo]
__device__ bf16 g_wq[(size_t)NDIM * KBIG];     // W: [hi,lo,hi]
__device__ bf16 g_wk[(size_t)NDIM * KBIG];
__device__ bf16 g_wv[(size_t)NDIM * KBIG];
__device__ bf16 g_wo[(size_t)NDIM * KBIG];

// ---------------------------------------------------------------------------
// helpers
// ---------------------------------------------------------------------------
__device__ __forceinline__ uint32_t smem_u32(const void* p) {
    uint32_t a;
    asm("{ .reg .u64 t; cvta.to.shared.u64 t, %1; cvt.u32.u64 %0, t; }"
        : "=r"(a) : "l"(p));
    return a;
}
__device__ __forceinline__ void cp16(uint32_t sa, const void* g) {
    asm volatile("cp.async.cg.shared.global [%0], [%1], 16;" :: "r"(sa), "l"(g));
}
#define CP_COMMIT() asm volatile("cp.async.commit_group;" ::: "memory")

__device__ __forceinline__ void ldsm4(uint32_t* r, uint32_t addr) {
    asm volatile("ldmatrix.sync.aligned.m8n8.x4.shared.b16 {%0,%1,%2,%3}, [%4];"
                 : "=r"(r[0]), "=r"(r[1]), "=r"(r[2]), "=r"(r[3]) : "r"(addr));
}
__device__ __forceinline__ void mma16816(float* c, const uint32_t* a,
                                         const uint32_t* b) {
    asm volatile(
        "mma.sync.aligned.m16n8k16.row.col.f32.bf16.bf16.f32 "
        "{%0,%1,%2,%3}, {%4,%5,%6,%7}, {%8,%9}, {%0,%1,%2,%3};"
        : "+f"(c[0]), "+f"(c[1]), "+f"(c[2]), "+f"(c[3])
        : "r"(a[0]), "r"(a[1]), "r"(a[2]), "r"(a[3]), "r"(b[0]), "r"(b[1]));
}
__device__ __forceinline__ uint32_t swz(uint32_t o) { return o ^ ((o >> 3) & 0x70); }
__device__ __forceinline__ uint32_t pack2(bf16 a, bf16 b) {
    return (uint32_t)*(uint16_t*)&a | ((uint32_t)*(uint16_t*)&b << 16);
}

// ---------------------------------------------------------------------------
// fp32 -> split-bf16 buffers. mode=0 (activation): [hi, hi, lo]
// mode=1 (weight): [hi, lo, hi].
// ---------------------------------------------------------------------------
__global__ __launch_bounds__(256)
void make_big(const float* __restrict__ src, bf16* __restrict__ dst, int mode) {
    size_t t = (size_t)blockIdx.x * 256 + threadIdx.x;
    size_t row = t >> 9;
    int col = (int)(t & 511) << 2;
    float4 x = *(const float4*)(src + row * 2048 + col);
    bf16 h[4], l[4];
    float xs[4] = {x.x, x.y, x.z, x.w};
#pragma unroll
    for (int i = 0; i < 4; i++) {
        h[i] = __float2bfloat16(xs[i]);
        l[i] = __float2bfloat16(xs[i] - __bfloat162float(h[i]));
    }
    bf16* d0 = dst + row * KBIG + col;
    uint32_t hp0 = pack2(h[0], h[1]), hp1 = pack2(h[2], h[3]);
    uint32_t lp0 = pack2(l[0], l[1]), lp1 = pack2(l[2], l[3]);
    ((uint32_t*)d0)[0] = hp0; ((uint32_t*)d0)[1] = hp1;
    if (mode == 0) {
        ((uint32_t*)(d0 + 2048))[0] = hp0; ((uint32_t*)(d0 + 2048))[1] = hp1;
        ((uint32_t*)(d0 + 4096))[0] = lp0; ((uint32_t*)(d0 + 4096))[1] = lp1;
    } else {
        ((uint32_t*)(d0 + 2048))[0] = lp0; ((uint32_t*)(d0 + 2048))[1] = lp1;
        ((uint32_t*)(d0 + 4096))[0] = hp0; ((uint32_t*)(d0 + 4096))[1] = hp1;
    }
}

// ---------------------------------------------------------------------------
// Shared GEMM mainloop: 128m x 256n block, K=6144 in 96 chunks of 64,
// 4-stage cp.async ring, mma.sync bf16. 8 warps as 2m x 4n (warp 64x64).
// ---------------------------------------------------------------------------
#define NSTG 4
#define STG_BYTES 49152   // A 16KB + B 32KB
#define GEMM_SMEM (NSTG * STG_BYTES)

__device__ __forceinline__ void gemm_mainloop(
    const bf16* __restrict__ A, const bf16* __restrict__ W,
    uint32_t data, int bm, int bn, float (&acc)[4][8][4],
    int tid, int wid, int lane) {
    const int m_base = (wid & 1) * 64;
    const int n_base = (wid >> 1) * 64;

#pragma unroll
    for (int c = 0; c < NSTG; c++) {
        uint32_t stg = data + c * STG_BYTES;
#pragma unroll
        for (int j = 0; j < 12; j++) {
            int idx = j * 256 + tid;
            int row = idx >> 3;
            int c16 = idx & 7;
            bool isB = row >= 128;
            int r = isB ? row - 128 : row;
            const bf16* src =
                (isB ? W + (size_t)(bn + r) * KBIG : A + (size_t)(bm + r) * KBIG)
                + c * 64 + c16 * 8;
            uint32_t off = swz((uint32_t)(r * 128 + c16 * 16));
            cp16(stg + (isB ? 16384 : 0) + off, src);
        }
        CP_COMMIT();
    }

    const int raL = lane & 15;
    const int akh = lane >> 4;
    const int rbL = (lane & 7) + ((lane & 16) >> 1);
    const int bkh = (lane >> 3) & 1;

    for (int i = 0; i < NCHUNK; i++) {
        int pend = NCHUNK - 1 - i; if (pend > NSTG - 1) pend = NSTG - 1;
        if (pend == 3)      asm volatile("cp.async.wait_group 3;" ::: "memory");
        else if (pend == 2) asm volatile("cp.async.wait_group 2;" ::: "memory");
        else if (pend == 1) asm volatile("cp.async.wait_group 1;" ::: "memory");
        else                asm volatile("cp.async.wait_group 0;" ::: "memory");
        __syncthreads();

        uint32_t sA = data + (i & 3) * STG_BYTES;
        uint32_t sB = sA + 16384;

#pragma unroll
        for (int ks = 0; ks < 4; ks++) {
            uint32_t a[4][4];
#pragma unroll
            for (int mt = 0; mt < 4; mt++) {
                int ra = m_base + mt * 16 + raL;
                uint32_t ck = (uint32_t)(ks * 2 + akh) ^ (uint32_t)(ra & 7);
                ldsm4(a[mt], sA + (uint32_t)(ra * 128) + (ck << 4));
            }
            uint32_t b[4][4];
#pragma unroll
            for (int nt2 = 0; nt2 < 4; nt2++) {
                int rb = n_base + nt2 * 16 + rbL;
                uint32_t ck = (uint32_t)(ks * 2 + bkh) ^ (uint32_t)(rb & 7);
                ldsm4(b[nt2], sB + (uint32_t)(rb * 128) + (ck << 4));
            }
#pragma unroll
            for (int mt = 0; mt < 4; mt++)
#pragma unroll
                for (int nt = 0; nt < 8; nt++)
                    mma16816(acc[mt][nt], a[mt], &b[nt >> 1][(nt & 1) * 2]);
        }
        __syncthreads();

        int nc = i + NSTG;
        if (nc < NCHUNK) {
            uint32_t stg = data + (i & 3) * STG_BYTES;
#pragma unroll
            for (int j = 0; j < 12; j++) {
                int idx = j * 256 + tid;
                int row = idx >> 3;
                int c16 = idx & 7;
                bool isB = row >= 128;
                int r = isB ? row - 128 : row;
                const bf16* src =
                    (isB ? W + (size_t)(bn + r) * KBIG : A + (size_t)(bm + r) * KBIG)
                    + nc * 64 + c16 * 8;
                uint32_t off = swz((uint32_t)(r * 128 + c16 * 16));
                cp16(stg + (isB ? 16384 : 0) + off, src);
            }
            CP_COMMIT();
        }
    }
}

// ---------------------------------------------------------------------------
// Merged QKV GEMM. grid (24, 128): wsel = x>>3 selects weight, bn=(x&7)*256.
// Q/K epilogue: paged bf16 hi/lo via smem transpose. V: transposed paged.
// ---------------------------------------------------------------------------
__global__ __launch_bounds__(256, 1)
void gemm_qkv(const bf16* __restrict__ A,
              const bf16* __restrict__ W0, const bf16* __restrict__ W1,
              const bf16* __restrict__ W2,
              const float* __restrict__ b0, const float* __restrict__ b1,
              const float* __restrict__ b2,
              bf16* __restrict__ qhi, bf16* __restrict__ qlo,
              bf16* __restrict__ khi, bf16* __restrict__ klo,
              bf16* __restrict__ vthi, bf16* __restrict__ vtlo) {
    extern __shared__ char dsm[];
    const uint32_t data = smem_u32(dsm);
    const int tid = threadIdx.x, wid = tid >> 5, lane = tid & 31;
    const int wsel = blockIdx.x >> 3;
    const int bn = (blockIdx.x & 7) << 8;
    const int bm = blockIdx.y << 7;
    const bf16* W = wsel == 0 ? W0 : wsel == 1 ? W1 : W2;
    const float* bias = wsel == 0 ? b0 : wsel == 1 ? b1 : b2;

    float acc[4][8][4];
#pragma unroll
    for (int mt = 0; mt < 4; mt++)
#pragma unroll
        for (int nt = 0; nt < 8; nt++)
#pragma unroll
            for (int r = 0; r < 4; r++) acc[mt][nt][r] = 0.f;

    gemm_mainloop(A, W, data, bm, bn, acc, tid, wid, lane);

    const int m_base = (wid & 1) * 64;
    const int n_base = (wid >> 1) * 64;

    // bias add
#pragma unroll
    for (int mt = 0; mt < 4; mt++)
#pragma unroll
        for (int nt = 0; nt < 8; nt++) {
            int col = bn + n_base + nt * 8 + (lane & 3) * 2;
            float bb0 = bias[col], bb1 = bias[col + 1];
            acc[mt][nt][0] += bb0; acc[mt][nt][1] += bb1;
            acc[mt][nt][2] += bb0; acc[mt][nt][3] += bb1;
        }

    const int b = bm >> 12, s0 = bm & 4095;
    const int page = s0 >> 8, par = (s0 >> 7) & 1;

    if (wsel < 2) {
        bf16* dhi = wsel ? khi : qhi;
        bf16* dlo = wsel ? klo : qlo;
        __syncthreads();
        float* smf = (float*)dsm;  // [c:128][r:132]
#pragma unroll 1
        for (int hh = 0; hh < 2; hh++) {
            if ((wid >> 2) == hh) {
                int cbase = n_base - hh * 128;
#pragma unroll
                for (int mt = 0; mt < 4; mt++) {
                    int r = m_base + mt * 16 + (lane >> 2);
#pragma unroll
                    for (int nt = 0; nt < 8; nt++) {
                        int c = cbase + nt * 8 + (lane & 3) * 2;
                        smf[c * 132 + r] = acc[mt][nt][0];
                        smf[(c + 1) * 132 + r] = acc[mt][nt][1];
                        smf[c * 132 + r + 8] = acc[mt][nt][2];
                        smf[(c + 1) * 132 + r + 8] = acc[mt][nt][3];
                    }
                }
            }
            __syncthreads();
            int head = (bn >> 7) + hh;
            size_t pb = ((size_t)((b * 16 + head) * 16 + page)) << 15;
            for (int cc = wid; cc < 128; cc += 8) {
                float4 v = *(const float4*)&smf[cc * 132 + lane * 4];
                bf16 h0 = __float2bfloat16(v.x), h1 = __float2bfloat16(v.y);
                bf16 h2 = __float2bfloat16(v.z), h3 = __float2bfloat16(v.w);
                bf16 l0 = __float2bfloat16(v.x - __bfloat162float(h0));
                bf16 l1 = __float2bfloat16(v.y - __bfloat162float(h1));
                bf16 l2 = __float2bfloat16(v.z - __bfloat162float(h2));
                bf16 l3 = __float2bfloat16(v.w - __bfloat162float(h3));
                size_t off = pb + (size_t)(2 * cc + par) * 128 + lane * 4;
                *(uint2*)(dhi + off) = make_uint2(pack2(h0, h1), pack2(h2, h3));
                *(uint2*)(dlo + off) = make_uint2(pack2(l0, l1), pack2(l2, l3));
            }
            __syncthreads();
        }
    } else {
        // V: transposed paged store [page][d2=r][p2=2c+par] direct from regs
#pragma unroll
        for (int nt = 0; nt < 8; nt++) {
            int nl = n_base + nt * 8 + (lane & 3) * 2;  // 0..255
            int hh = nl >> 7;
            int cw = nl & 127;
            int head = (bn >> 7) + hh;
            size_t pb = ((size_t)((b * 16 + head) * 16 + page)) << 15;
#pragma unroll
            for (int mt = 0; mt < 4; mt++) {
                int r0 = m_base + mt * 16 + (lane >> 2);
#pragma unroll
                for (int q = 0; q < 2; q++) {
                    int r = r0 + q * 8;
#pragma unroll
                    for (int e = 0; e < 2; e++) {
                        float v = acc[mt][nt][q * 2 + e];
                        bf16 h = __float2bfloat16(v);
                        bf16 l = __float2bfloat16(v - __bfloat162float(h));
                        size_t off = pb + (size_t)r * 256 + 2 * (cw + e) + par;
                        vthi[off] = h;
                        vtlo[off] = l;
                    }
                }
            }
        }
    }
}

// ---------------------------------------------------------------------------
// Wo GEMM: plain fp32 output
// ---------------------------------------------------------------------------
__global__ __launch_bounds__(256, 1)
void gemm_wo(const bf16* __restrict__ A, const bf16* __restrict__ W,
             const float* __restrict__ bias, float* __restrict__ C) {
    extern __shared__ char dsm[];
    const uint32_t data = smem_u32(dsm);
    const int tid = threadIdx.x, wid = tid >> 5, lane = tid & 31;
    const int bn = blockIdx.x << 8, bm = blockIdx.y << 7;

    float acc[4][8][4];
#pragma unroll
    for (int mt = 0; mt < 4; mt++)
#pragma unroll
        for (int nt = 0; nt < 8; nt++)
#pragma unroll
            for (int r = 0; r < 4; r++) acc[mt][nt][r] = 0.f;

    gemm_mainloop(A, W, data, bm, bn, acc, tid, wid, lane);

    const int m_base = (wid & 1) * 64;
    const int n_base = (wid >> 1) * 64;
#pragma unroll
    for (int mt = 0; mt < 4; mt++) {
        int r0 = bm + m_base + mt * 16 + (lane >> 2);
#pragma unroll
        for (int nt = 0; nt < 8; nt++) {
            int col = bn + n_base + nt * 8 + (lane & 3) * 2;
            float bb0 = bias[col], bb1 = bias[col + 1];
            float* p0 = C + (size_t)r0 * NDIM + col;
            float* p1 = p0 + (size_t)8 * NDIM;
            *(float2*)p0 = make_float2(acc[mt][nt][0] + bb0, acc[mt][nt][1] + bb1);
            *(float2*)p1 = make_float2(acc[mt][nt][2] + bb0, acc[mt][nt][3] + bb1);
        }
    }
}

// ---------------------------------------------------------------------------
// HMMA attention. Block = (qt 0..3, h2 0..15, x2 0..63), 256 threads.
// Smem: Q hi/lo [2][2kc][64][128B] 32KB @0; K hi/lo [2][2kc][256][128B] 128KB
// @32768; S fp32 [64][260] 66560B @163840. Phase 2: P [2][4kc][64][128B]
// 64KB @32768; V chunks [2buf][128][128B] 32KB @98304.
// ---------------------------------------------------------------------------
#define ATT_SQ 0
#define ATT_SK 32768
#define ATT_SP 32768
#define ATT_SV 98304
#define ATT_SS 163840
#define ATT_SMEM 230400
#define SST 260

__global__ __launch_bounds__(256, 1)
void attn2(const bf16* __restrict__ qhi, const bf16* __restrict__ qlo,
           const bf16* __restrict__ khi, const bf16* __restrict__ klo,
           const bf16* __restrict__ vthi, const bf16* __restrict__ vtlo,
           bf16* __restrict__ cbig) {
    extern __shared__ char smraw[];
    const uint32_t sb = smem_u32(smraw);
    float* sS = (float*)(smraw + ATT_SS);

    const float SCALE = 0.08838834764831843f;
    const int qt = blockIdx.x, h2 = blockIdx.y, x2 = blockIdx.z;
    const int tid = threadIdx.x, wid = tid >> 5, lane = tid & 31;
    const size_t pagebase = ((size_t)(x2 * 16 + h2)) << 15;

    const int raL = lane & 15, akh = lane >> 4;
    const int rbL = (lane & 7) + ((lane & 16) >> 1), bkh = (lane >> 3) & 1;

    // Phase 1 loads: Q (64 rows) + K (256 rows), hi & lo
#pragma unroll
    for (int q = 0; q < 8; q++) {
        int idx = q * 256 + tid;
        int prec = idx >> 10, rem = idx & 1023;
        int r = rem >> 4, kc = (rem >> 3) & 1, c16 = rem & 7;
        const bf16* s = (prec ? qlo : qhi) + pagebase +
                        (size_t)(qt * 64 + r) * 128 + kc * 64 + c16 * 8;
        cp16(sb + ATT_SQ + prec * 16384 + kc * 8192 + swz(r * 128 + c16 * 16), s);
    }
#pragma unroll
    for (int q = 0; q < 32; q++) {
        int idx = q * 256 + tid;
        int prec = idx >> 12, rem = idx & 4095;
        int r = rem >> 4, kc = (rem >> 3) & 1, c16 = rem & 7;
        const bf16* s = (prec ? klo : khi) + pagebase + (size_t)r * 128 +
                        kc * 64 + c16 * 8;
        cp16(sb + ATT_SK + prec * 65536 + kc * 32768 + swz(r * 128 + c16 * 16), s);
    }
    CP_COMMIT();
    asm volatile("cp.async.wait_group 0;" ::: "memory");
    __syncthreads();

    // QK: S[64][256] = 3-term split. warp tile 32m x 64n
    {
        const int m_base = (wid & 1) * 32;
        const int n_base = (wid >> 1) * 64;
        float acc[2][8][4];
#pragma unroll
        for (int mt = 0; mt < 2; mt++)
#pragma unroll
            for (int nt = 0; nt < 8; nt++)
#pragma unroll
                for (int r = 0; r < 4; r++) acc[mt][nt][r] = 0.f;

        const int ap[3] = {0, 0, 1}, bp[3] = {0, 1, 0};
#pragma unroll 1
        for (int t = 0; t < 3; t++) {
            uint32_t Ab = sb + ATT_SQ + ap[t] * 16384;
            uint32_t Bb = sb + ATT_SK + bp[t] * 65536;
#pragma unroll
            for (int kc = 0; kc < 2; kc++) {
#pragma unroll
                for (int ks = 0; ks < 4; ks++) {
                    uint32_t a[2][4];
#pragma unroll
                    for (int mt = 0; mt < 2; mt++) {
                        int ra = m_base + mt * 16 + raL;
                        uint32_t ck = (uint32_t)(ks * 2 + akh) ^ (uint32_t)(ra & 7);
                        ldsm4(a[mt], Ab + kc * 8192 + (uint32_t)(ra * 128) + (ck << 4));
                    }
                    uint32_t bfr[4][4];
#pragma unroll
                    for (int nt2 = 0; nt2 < 4; nt2++) {
                        int rb = n_base + nt2 * 16 + rbL;
                        uint32_t ck = (uint32_t)(ks * 2 + bkh) ^ (uint32_t)(rb & 7);
                        ldsm4(bfr[nt2], Bb + kc * 32768 + (uint32_t)(rb * 128) + (ck << 4));
                    }
#pragma unroll
                    for (int mt = 0; mt < 2; mt++)
#pragma unroll
                        for (int nt = 0; nt < 8; nt++)
                            mma16816(acc[mt][nt], a[mt], &bfr[nt >> 1][(nt & 1) * 2]);
                }
            }
        }
        // store S * SCALE
#pragma unroll
        for (int mt = 0; mt < 2; mt++) {
            int r = m_base + mt * 16 + (lane >> 2);
#pragma unroll
            for (int nt = 0; nt < 8; nt++) {
                int c = n_base + nt * 8 + (lane & 3) * 2;
                sS[r * SST + c] = acc[mt][nt][0] * SCALE;
                sS[r * SST + c + 1] = acc[mt][nt][1] * SCALE;
                sS[(r + 8) * SST + c] = acc[mt][nt][2] * SCALE;
                sS[(r + 8) * SST + c + 1] = acc[mt][nt][3] * SCALE;
            }
        }
    }
    __syncthreads();

    // prefetch V chunks 0 (Vhi kt0) and 1 (Vlo kt0)
#pragma unroll
    for (int cch = 0; cch < 2; cch++) {
        const bf16* base = (cch ? vtlo : vthi) + pagebase;
#pragma unroll
        for (int q = 0; q < 4; q++) {
            int idx = q * 256 + tid;
            int r = idx >> 3, c16 = idx & 7;
            cp16(sb + ATT_SV + cch * 16384 + swz(r * 128 + c16 * 16),
                 base + (size_t)r * 256 + 0 * 64 + c16 * 8);
        }
        CP_COMMIT();
    }

    // softmax: warp per row
    for (int r = wid; r < 64; r += 8) {
        float v[8];
        float m = -3.4e38f;
#pragma unroll
        for (int c = 0; c < 8; c++) {
            v[c] = sS[r * SST + 32 * c + lane];
            m = fmaxf(m, v[c]);
        }
#pragma unroll
        for (int o = 16; o; o >>= 1) m = fmaxf(m, __shfl_xor_sync(0xffffffffu, m, o));
        float sum = 0.f;
#pragma unroll
        for (int c = 0; c < 8; c++) {
            v[c] = __expf(v[c] - m);
            sum += v[c];
        }
#pragma unroll
        for (int o = 16; o; o >>= 1) sum += __shfl_xor_sync(0xffffffffu, sum, o);
        float inv = 1.0f / sum;
#pragma unroll
        for (int c = 0; c < 8; c++) sS[r * SST + 32 * c + lane] = v[c] * inv;
    }
    __syncthreads();

    // P convert: S fp32 -> P hi/lo bf16 sub-tiles [prec][kc4][64][128B]
    {
        int m = tid >> 2, kcq = tid & 3;
        const float* srow = sS + m * SST + kcq * 64;
        uint32_t dh = sb + ATT_SP + kcq * 8192;
#pragma unroll
        for (int j = 0; j < 32; j++) {
            float s0 = srow[2 * j], s1 = srow[2 * j + 1];
            bf16 h0 = __float2bfloat16(s0), h1 = __float2bfloat16(s1);
            bf16 l0 = __float2bfloat16(s0 - __bfloat162float(h0));
            bf16 l1 = __float2bfloat16(s1 - __bfloat162float(h1));
            uint32_t off = swz((uint32_t)(m * 128 + 4 * j));
            *(uint32_t*)(smraw + (dh - sb) + off) = pack2(h0, h1);
            *(uint32_t*)(smraw + (dh - sb) + 32768 + off) = pack2(l0, l1);
        }
    }
    __syncthreads();

    // PV: ctx[64][128] = 3-term split, V streamed in 8 chunks.
    float acc2[2][4][4];
#pragma unroll
    for (int mt = 0; mt < 2; mt++)
#pragma unroll
        for (int nt = 0; nt < 4; nt++)
#pragma unroll
            for (int r = 0; r < 4; r++) acc2[mt][nt][r] = 0.f;

    const int m2 = (wid & 1) * 32;
    const int n2 = (wid >> 1) * 32;

#pragma unroll 1
    for (int j = 0; j < 8; j++) {
        int kt = j >> 1, vp = j & 1;
        if (j < 7) asm volatile("cp.async.wait_group 1;" ::: "memory");
        else       asm volatile("cp.async.wait_group 0;" ::: "memory");
        __syncthreads();

        uint32_t Vb = sb + ATT_SV + (j & 1) * 16384;
        int npass = vp ? 1 : 2;
#pragma unroll 1
        for (int p = 0; p < npass; p++) {
            int pp = vp ? 0 : p;  // P precision for this pass
            uint32_t Pb = sb + ATT_SP + pp * 32768 + kt * 8192;
#pragma unroll
            for (int ks = 0; ks < 4; ks++) {
                uint32_t a[2][4];
#pragma unroll
                for (int mt = 0; mt < 2; mt++) {
                    int ra = m2 + mt * 16 + raL;
                    uint32_t ck = (uint32_t)(ks * 2 + akh) ^ (uint32_t)(ra & 7);
                    ldsm4(a[mt], Pb + (uint32_t)(ra * 128) + (ck << 4));
                }
                uint32_t bfr[2][4];
#pragma unroll
                for (int nt2 = 0; nt2 < 2; nt2++) {
                    int rb = n2 + nt2 * 16 + rbL;
                    uint32_t ck = (uint32_t)(ks * 2 + bkh) ^ (uint32_t)(rb & 7);
                    ldsm4(bfr[nt2], Vb + (uint32_t)(rb * 128) + (ck << 4));
                }
#pragma unroll
                for (int mt = 0; mt < 2; mt++)
#pragma unroll
                    for (int nt = 0; nt < 4; nt++)
                        mma16816(acc2[mt][nt], a[mt], &bfr[nt >> 1][(nt & 1) * 2]);
            }
        }
        __syncthreads();

        int nchunk = j + 2;
        if (nchunk < 8) {
            int kt2 = nchunk >> 1, vp2 = nchunk & 1;
            const bf16* base = (vp2 ? vtlo : vthi) + pagebase;
#pragma unroll
            for (int q = 0; q < 4; q++) {
                int idx = q * 256 + tid;
                int r = idx >> 3, c16 = idx & 7;
                cp16(sb + ATT_SV + (j & 1) * 16384 + swz(r * 128 + c16 * 16),
                     base + (size_t)r * 256 + kt2 * 64 + c16 * 8);
            }
            CP_COMMIT();
        }
    }

    // Epilogue: ctx -> cbig [hi, hi, lo]
    const int b = x2 >> 4, head = x2 & 15;
#pragma unroll
    for (int mt = 0; mt < 2; mt++) {
        int r0 = qt * 64 + m2 + mt * 16 + (lane >> 2);
#pragma unroll
        for (int nt = 0; nt < 4; nt++) {
            int colb = h2 * 128 + n2 + nt * 8 + (lane & 3) * 2;
#pragma unroll
            for (int q = 0; q < 2; q++) {
                int r = r0 + q * 8;
                float v0 = acc2[mt][nt][q * 2], v1 = acc2[mt][nt][q * 2 + 1];
                bf16 h0 = __float2bfloat16(v0), h1 = __float2bfloat16(v1);
                bf16 l0 = __float2bfloat16(v0 - __bfloat162float(h0));
                bf16 l1 = __float2bfloat16(v1 - __bfloat162float(h1));
                uint32_t hp = pack2(h0, h1), lp = pack2(l0, l1);
                bf16* d = cbig + (size_t)(b * 4096 + head * 256 + r) * KBIG + colb;
                *(uint32_t*)d = hp;
                *(uint32_t*)(d + 2048) = hp;
                *(uint32_t*)(d + 4096) = lp;
            }
        }
    }
}

// ---------------------------------------------------------------------------
extern "C" void kernel_launch(void* const* d_in, const int* in_sizes, int n_in,
                              void* d_out, int out_size) {
    const float* hidden = (const float*)d_in[0];
    const float* Wq = (const float*)d_in[1];
    const float* bq = (const float*)d_in[2];
    const float* Wk = (const float*)d_in[3];
    const float* bk = (const float*)d_in[4];
    const float* Wv = (const float*)d_in[5];
    const float* bv = (const float*)d_in[6];
    const float* Wo = (const float*)d_in[7];
    const float* bo = (const float*)d_in[8];
    float* out = (float*)d_out;

    bf16 *hbig, *cbig, *wq, *wk, *wv, *wo;
    bf16 *qhi, *qlo, *khi, *klo, *vthi, *vtlo;
    cudaGetSymbolAddress((void**)&hbig, g_hbig);
    cudaGetSymbolAddress((void**)&cbig, g_cbig);
    cudaGetSymbolAddress((void**)&wq, g_wq);
    cudaGetSymbolAddress((void**)&wk, g_wk);
    cudaGetSymbolAddress((void**)&wv, g_wv);
    cudaGetSymbolAddress((void**)&wo, g_wo);
    cudaGetSymbolAddress((void**)&qhi, g_qhi);
    cudaGetSymbolAddress((void**)&qlo, g_qlo);
    cudaGetSymbolAddress((void**)&khi, g_khi);
    cudaGetSymbolAddress((void**)&klo, g_klo);
    cudaGetSymbolAddress((void**)&vthi, g_vthi);
    cudaGetSymbolAddress((void**)&vtlo, g_vtlo);

    cudaFuncSetAttribute(gemm_qkv, cudaFuncAttributeMaxDynamicSharedMemorySize,
                         GEMM_SMEM);
    cudaFuncSetAttribute(gemm_wo, cudaFuncAttributeMaxDynamicSharedMemorySize,
                         GEMM_SMEM);
    cudaFuncSetAttribute(attn2, cudaFuncAttributeMaxDynamicSharedMemorySize,
                         ATT_SMEM);

    make_big<<<4096, 256>>>(Wq, wq, 1);
    make_big<<<4096, 256>>>(Wk, wk, 1);
    make_big<<<4096, 256>>>(Wv, wv, 1);
    make_big<<<4096, 256>>>(Wo, wo, 1);
    make_big<<<32768, 256>>>(hidden, hbig, 0);

    gemm_qkv<<<dim3(24, 128), 256, GEMM_SMEM>>>(
        hbig, wq, wk, wv, bq, bk, bv, qhi, qlo, khi, klo, vthi, vtlo);
    attn2<<<dim3(4, 16, 64), 256, ATT_SMEM>>>(qhi, qlo, khi, klo, vthi, vtlo, cbig);
    gemm_wo<<<dim3(8, 128), 256, GEMM_SMEM>>>(cbig, wo, bo, out);
}

// round 6
// speedup vs baseline: 2.8406x; 1.0125x over previous
#include <cuda_runtime.h>
#include <cuda_bf16.h>
#include <cstdint>

typedef __nv_bfloat16 bf16;

// Problem constants: B=4, S=4096, HID=2048, H=16, P=256, D=128, N=16
#define NELEM 33554432u   // 4*4096*2048
#define KBIG 6144
#define NCHUNK 96         // KBIG / 64
#define MDIM 16384
#define NDIM 2048

// paged bf16 hi/lo buffers: [page=(b*16+head)*16+n][256][128]
__device__ bf16 g_qhi[NELEM];
__device__ bf16 g_qlo[NELEM];
__device__ bf16 g_khi[NELEM];
__device__ bf16 g_klo[NELEM];
__device__ bf16 g_vthi[NELEM];  // transposed: [page][d2:128][p2:256]
__device__ bf16 g_vtlo[NELEM];

__device__ bf16 g_hbig[(size_t)MDIM * KBIG];   // hidden: [hi,hi,lo]
__device__ bf16 g_cbig[(size_t)MDIM * KBIG];   // ctx:    [hi,hi,lo]
__device__ bf16 g_wq[(size_t)NDIM * KBIG];     // W: [hi,lo,hi]
__device__ bf16 g_wk[(size_t)NDIM * KBIG];
__device__ bf16 g_wv[(size_t)NDIM * KBIG];
__device__ bf16 g_wo[(size_t)NDIM * KBIG];

// ---------------------------------------------------------------------------
// helpers
// ---------------------------------------------------------------------------
__device__ __forceinline__ uint32_t smem_u32(const void* p) {
    uint32_t a;
    asm("{ .reg .u64 t; cvta.to.shared.u64 t, %1; cvt.u32.u64 %0, t; }"
        : "=r"(a) : "l"(p));
    return a;
}
__device__ __forceinline__ void cp16(uint32_t sa, const void* g) {
    asm volatile("cp.async.cg.shared.global [%0], [%1], 16;" :: "r"(sa), "l"(g));
}
#define CP_COMMIT() asm volatile("cp.async.commit_group;" ::: "memory")

__device__ __forceinline__ void ldsm4(uint32_t* r, uint32_t addr) {
    asm volatile("ldmatrix.sync.aligned.m8n8.x4.shared.b16 {%0,%1,%2,%3}, [%4];"
                 : "=r"(r[0]), "=r"(r[1]), "=r"(r[2]), "=r"(r[3]) : "r"(addr));
}
__device__ __forceinline__ void mma16816(float* c, const uint32_t* a,
                                         const uint32_t* b) {
    asm volatile(
        "mma.sync.aligned.m16n8k16.row.col.f32.bf16.bf16.f32 "
        "{%0,%1,%2,%3}, {%4,%5,%6,%7}, {%8,%9}, {%0,%1,%2,%3};"
        : "+f"(c[0]), "+f"(c[1]), "+f"(c[2]), "+f"(c[3])
        : "r"(a[0]), "r"(a[1]), "r"(a[2]), "r"(a[3]), "r"(b[0]), "r"(b[1]));
}
__device__ __forceinline__ uint32_t swz(uint32_t o) { return o ^ ((o >> 3) & 0x70); }
__device__ __forceinline__ uint32_t pack2(bf16 a, bf16 b) {
    return (uint32_t)*(uint16_t*)&a | ((uint32_t)*(uint16_t*)&b << 16);
}

// ---------------------------------------------------------------------------
// fp32 -> split-bf16 buffers. mode=0 (activation): [hi, hi, lo]
// mode=1 (weight): [hi, lo, hi].
// ---------------------------------------------------------------------------
__global__ __launch_bounds__(256)
void make_big(const float* __restrict__ src, bf16* __restrict__ dst, int mode) {
    size_t t = (size_t)blockIdx.x * 256 + threadIdx.x;
    size_t row = t >> 9;
    int col = (int)(t & 511) << 2;
    float4 x = *(const float4*)(src + row * 2048 + col);
    bf16 h[4], l[4];
    float xs[4] = {x.x, x.y, x.z, x.w};
#pragma unroll
    for (int i = 0; i < 4; i++) {
        h[i] = __float2bfloat16(xs[i]);
        l[i] = __float2bfloat16(xs[i] - __bfloat162float(h[i]));
    }
    bf16* d0 = dst + row * KBIG + col;
    uint32_t hp0 = pack2(h[0], h[1]), hp1 = pack2(h[2], h[3]);
    uint32_t lp0 = pack2(l[0], l[1]), lp1 = pack2(l[2], l[3]);
    ((uint32_t*)d0)[0] = hp0; ((uint32_t*)d0)[1] = hp1;
    if (mode == 0) {
        ((uint32_t*)(d0 + 2048))[0] = hp0; ((uint32_t*)(d0 + 2048))[1] = hp1;
        ((uint32_t*)(d0 + 4096))[0] = lp0; ((uint32_t*)(d0 + 4096))[1] = lp1;
    } else {
        ((uint32_t*)(d0 + 2048))[0] = lp0; ((uint32_t*)(d0 + 2048))[1] = lp1;
        ((uint32_t*)(d0 + 4096))[0] = hp0; ((uint32_t*)(d0 + 4096))[1] = hp1;
    }
}

// ---------------------------------------------------------------------------
// Shared GEMM mainloop: 128m x 256n block, K=6144 in 96 chunks of 64,
// 4-stage cp.async ring, SINGLE __syncthreads per chunk (CUTLASS multistage):
// wait -> sync -> prefetch chunk i+3 into stage consumed at iter i-1 ->
// compute chunk i. 8 warps as 2m x 4n (warp 64x64).
// ---------------------------------------------------------------------------
#define NSTG 4
#define STG_BYTES 49152   // A 16KB + B 32KB
#define GEMM_SMEM (NSTG * STG_BYTES)

__device__ __forceinline__ void load_chunk(
    const bf16* __restrict__ A, const bf16* __restrict__ W,
    uint32_t stg, int bm, int bn, int chunk, int tid) {
#pragma unroll
    for (int j = 0; j < 12; j++) {
        int idx = j * 256 + tid;
        int row = idx >> 3;
        int c16 = idx & 7;
        bool isB = row >= 128;
        int r = isB ? row - 128 : row;
        const bf16* src =
            (isB ? W + (size_t)(bn + r) * KBIG : A + (size_t)(bm + r) * KBIG)
            + chunk * 64 + c16 * 8;
        uint32_t off = swz((uint32_t)(r * 128 + c16 * 16));
        cp16(stg + (isB ? 16384 : 0) + off, src);
    }
    CP_COMMIT();
}

__device__ __forceinline__ void gemm_mainloop(
    const bf16* __restrict__ A, const bf16* __restrict__ W,
    uint32_t data, int bm, int bn, float (&acc)[4][8][4],
    int tid, int wid, int lane) {
    const int m_base = (wid & 1) * 64;
    const int n_base = (wid >> 1) * 64;

    // Prologue: chunks 0..2 -> stages 0..2
#pragma unroll
    for (int c = 0; c < NSTG - 1; c++)
        load_chunk(A, W, data + c * STG_BYTES, bm, bn, c, tid);

    const int raL = lane & 15;
    const int akh = lane >> 4;
    const int rbL = (lane & 7) + ((lane & 16) >> 1);
    const int bkh = (lane >> 3) & 1;

    for (int i = 0; i < NCHUNK; i++) {
        // wait until chunk i resident: allowed pending = min(NSTG-2, last-i)
        int pend = NCHUNK - 1 - i; if (pend > NSTG - 2) pend = NSTG - 2;
        if (pend == 2)      asm volatile("cp.async.wait_group 2;" ::: "memory");
        else if (pend == 1) asm volatile("cp.async.wait_group 1;" ::: "memory");
        else                asm volatile("cp.async.wait_group 0;" ::: "memory");
        __syncthreads();

        // prefetch chunk i+NSTG-1 into stage (i+NSTG-1)&3 == (i-1)&3,
        // consumed at iter i-1 (barrier above proves reads complete)
        int nc = i + NSTG - 1;
        if (nc < NCHUNK)
            load_chunk(A, W, data + (nc & 3) * STG_BYTES, bm, bn, nc, tid);

        uint32_t sA = data + (i & 3) * STG_BYTES;
        uint32_t sB = sA + 16384;

#pragma unroll
        for (int ks = 0; ks < 4; ks++) {
            uint32_t a[4][4];
#pragma unroll
            for (int mt = 0; mt < 4; mt++) {
                int ra = m_base + mt * 16 + raL;
                uint32_t ck = (uint32_t)(ks * 2 + akh) ^ (uint32_t)(ra & 7);
                ldsm4(a[mt], sA + (uint32_t)(ra * 128) + (ck << 4));
            }
            uint32_t b[4][4];
#pragma unroll
            for (int nt2 = 0; nt2 < 4; nt2++) {
                int rb = n_base + nt2 * 16 + rbL;
                uint32_t ck = (uint32_t)(ks * 2 + bkh) ^ (uint32_t)(rb & 7);
                ldsm4(b[nt2], sB + (uint32_t)(rb * 128) + (ck << 4));
            }
#pragma unroll
            for (int mt = 0; mt < 4; mt++)
#pragma unroll
                for (int nt = 0; nt < 8; nt++)
                    mma16816(acc[mt][nt], a[mt], &b[nt >> 1][(nt & 1) * 2]);
        }
    }
    __syncthreads();  // protect smem before epilogue reuse
}

// ---------------------------------------------------------------------------
// Merged QKV GEMM. grid (24, 128): wsel = x>>3 selects weight, bn=(x&7)*256.
// Q/K epilogue: paged bf16 hi/lo via smem transpose. V: transposed paged.
// ---------------------------------------------------------------------------
__global__ __launch_bounds__(256, 1)
void gemm_qkv(const bf16* __restrict__ A,
              const bf16* __restrict__ W0, const bf16* __restrict__ W1,
              const bf16* __restrict__ W2,
              const float* __restrict__ b0, const float* __restrict__ b1,
              const float* __restrict__ b2,
              bf16* __restrict__ qhi, bf16* __restrict__ qlo,
              bf16* __restrict__ khi, bf16* __restrict__ klo,
              bf16* __restrict__ vthi, bf16* __restrict__ vtlo) {
    extern __shared__ char dsm[];
    const uint32_t data = smem_u32(dsm);
    const int tid = threadIdx.x, wid = tid >> 5, lane = tid & 31;
    const int wsel = blockIdx.x >> 3;
    const int bn = (blockIdx.x & 7) << 8;
    const int bm = blockIdx.y << 7;
    const bf16* W = wsel == 0 ? W0 : wsel == 1 ? W1 : W2;
    const float* bias = wsel == 0 ? b0 : wsel == 1 ? b1 : b2;

    float acc[4][8][4];
#pragma unroll
    for (int mt = 0; mt < 4; mt++)
#pragma unroll
        for (int nt = 0; nt < 8; nt++)
#pragma unroll
            for (int r = 0; r < 4; r++) acc[mt][nt][r] = 0.f;

    gemm_mainloop(A, W, data, bm, bn, acc, tid, wid, lane);

    const int m_base = (wid & 1) * 64;
    const int n_base = (wid >> 1) * 64;

    // bias add
#pragma unroll
    for (int mt = 0; mt < 4; mt++)
#pragma unroll
        for (int nt = 0; nt < 8; nt++) {
            int col = bn + n_base + nt * 8 + (lane & 3) * 2;
            float bb0 = bias[col], bb1 = bias[col + 1];
            acc[mt][nt][0] += bb0; acc[mt][nt][1] += bb1;
            acc[mt][nt][2] += bb0; acc[mt][nt][3] += bb1;
        }

    const int b = bm >> 12, s0 = bm & 4095;
    const int page = s0 >> 8, par = (s0 >> 7) & 1;

    if (wsel < 2) {
        bf16* dhi = wsel ? khi : qhi;
        bf16* dlo = wsel ? klo : qlo;
        float* smf = (float*)dsm;  // [c:128][r:132]
#pragma unroll 1
        for (int hh = 0; hh < 2; hh++) {
            if ((wid >> 2) == hh) {
                int cbase = n_base - hh * 128;
#pragma unroll
                for (int mt = 0; mt < 4; mt++) {
                    int r = m_base + mt * 16 + (lane >> 2);
#pragma unroll
                    for (int nt = 0; nt < 8; nt++) {
                        int c = cbase + nt * 8 + (lane & 3) * 2;
                        smf[c * 132 + r] = acc[mt][nt][0];
                        smf[(c + 1) * 132 + r] = acc[mt][nt][1];
                        smf[c * 132 + r + 8] = acc[mt][nt][2];
                        smf[(c + 1) * 132 + r + 8] = acc[mt][nt][3];
                    }
                }
            }
            __syncthreads();
            int head = (bn >> 7) + hh;
            size_t pb = ((size_t)((b * 16 + head) * 16 + page)) << 15;
            for (int cc = wid; cc < 128; cc += 8) {
                float4 v = *(const float4*)&smf[cc * 132 + lane * 4];
                bf16 h0 = __float2bfloat16(v.x), h1 = __float2bfloat16(v.y);
                bf16 h2 = __float2bfloat16(v.z), h3 = __float2bfloat16(v.w);
                bf16 l0 = __float2bfloat16(v.x - __bfloat162float(h0));
                bf16 l1 = __float2bfloat16(v.y - __bfloat162float(h1));
                bf16 l2 = __float2bfloat16(v.z - __bfloat162float(h2));
                bf16 l3 = __float2bfloat16(v.w - __bfloat162float(h3));
                size_t off = pb + (size_t)(2 * cc + par) * 128 + lane * 4;
                *(uint2*)(dhi + off) = make_uint2(pack2(h0, h1), pack2(h2, h3));
                *(uint2*)(dlo + off) = make_uint2(pack2(l0, l1), pack2(l2, l3));
            }
            __syncthreads();
        }
    } else {
        // V: transposed paged store [page][d2=r][p2=2c+par] direct from regs
#pragma unroll
        for (int nt = 0; nt < 8; nt++) {
            int nl = n_base + nt * 8 + (lane & 3) * 2;  // 0..255
            int hh = nl >> 7;
            int cw = nl & 127;
            int head = (bn >> 7) + hh;
            size_t pb = ((size_t)((b * 16 + head) * 16 + page)) << 15;
#pragma unroll
            for (int mt = 0; mt < 4; mt++) {
                int r0 = m_base + mt * 16 + (lane >> 2);
#pragma unroll
                for (int q = 0; q < 2; q++) {
                    int r = r0 + q * 8;
#pragma unroll
                    for (int e = 0; e < 2; e++) {
                        float v = acc[mt][nt][q * 2 + e];
                        bf16 h = __float2bfloat16(v);
                        bf16 l = __float2bfloat16(v - __bfloat162float(h));
                        size_t off = pb + (size_t)r * 256 + 2 * (cw + e) + par;
                        vthi[off] = h;
                        vtlo[off] = l;
                    }
                }
            }
        }
    }
}

// ---------------------------------------------------------------------------
// Wo GEMM: plain fp32 output
// ---------------------------------------------------------------------------
__global__ __launch_bounds__(256, 1)
void gemm_wo(const bf16* __restrict__ A, const bf16* __restrict__ W,
             const float* __restrict__ bias, float* __restrict__ C) {
    extern __shared__ char dsm[];
    const uint32_t data = smem_u32(dsm);
    const int tid = threadIdx.x, wid = tid >> 5, lane = tid & 31;
    const int bn = blockIdx.x << 8, bm = blockIdx.y << 7;

    float acc[4][8][4];
#pragma unroll
    for (int mt = 0; mt < 4; mt++)
#pragma unroll
        for (int nt = 0; nt < 8; nt++)
#pragma unroll
            for (int r = 0; r < 4; r++) acc[mt][nt][r] = 0.f;

    gemm_mainloop(A, W, data, bm, bn, acc, tid, wid, lane);

    const int m_base = (wid & 1) * 64;
    const int n_base = (wid >> 1) * 64;
#pragma unroll
    for (int mt = 0; mt < 4; mt++) {
        int r0 = bm + m_base + mt * 16 + (lane >> 2);
#pragma unroll
        for (int nt = 0; nt < 8; nt++) {
            int col = bn + n_base + nt * 8 + (lane & 3) * 2;
            float bb0 = bias[col], bb1 = bias[col + 1];
            float* p0 = C + (size_t)r0 * NDIM + col;
            float* p1 = p0 + (size_t)8 * NDIM;
            *(float2*)p0 = make_float2(acc[mt][nt][0] + bb0, acc[mt][nt][1] + bb1);
            *(float2*)p1 = make_float2(acc[mt][nt][2] + bb0, acc[mt][nt][3] + bb1);
        }
    }
}

// ---------------------------------------------------------------------------
// HMMA attention. Block = (qt 0..3, h2 0..15, x2 0..63), 256 threads.
// ---------------------------------------------------------------------------
#define ATT_SQ 0
#define ATT_SK 32768
#define ATT_SP 32768
#define ATT_SV 98304
#define ATT_SS 163840
#define ATT_SMEM 230400
#define SST 260

__global__ __launch_bounds__(256, 1)
void attn2(const bf16* __restrict__ qhi, const bf16* __restrict__ qlo,
           const bf16* __restrict__ khi, const bf16* __restrict__ klo,
           const bf16* __restrict__ vthi, const bf16* __restrict__ vtlo,
           bf16* __restrict__ cbig) {
    extern __shared__ char smraw[];
    const uint32_t sb = smem_u32(smraw);
    float* sS = (float*)(smraw + ATT_SS);

    const float SCALE = 0.08838834764831843f;
    const int qt = blockIdx.x, h2 = blockIdx.y, x2 = blockIdx.z;
    const int tid = threadIdx.x, wid = tid >> 5, lane = tid & 31;
    const size_t pagebase = ((size_t)(x2 * 16 + h2)) << 15;

    const int raL = lane & 15, akh = lane >> 4;
    const int rbL = (lane & 7) + ((lane & 16) >> 1), bkh = (lane >> 3) & 1;

    // Phase 1 loads: Q (64 rows) + K (256 rows), hi & lo
#pragma unroll
    for (int q = 0; q < 8; q++) {
        int idx = q * 256 + tid;
        int prec = idx >> 10, rem = idx & 1023;
        int r = rem >> 4, kc = (rem >> 3) & 1, c16 = rem & 7;
        const bf16* s = (prec ? qlo : qhi) + pagebase +
                        (size_t)(qt * 64 + r) * 128 + kc * 64 + c16 * 8;
        cp16(sb + ATT_SQ + prec * 16384 + kc * 8192 + swz(r * 128 + c16 * 16), s);
    }
#pragma unroll
    for (int q = 0; q < 32; q++) {
        int idx = q * 256 + tid;
        int prec = idx >> 12, rem = idx & 4095;
        int r = rem >> 4, kc = (rem >> 3) & 1, c16 = rem & 7;
        const bf16* s = (prec ? klo : khi) + pagebase + (size_t)r * 128 +
                        kc * 64 + c16 * 8;
        cp16(sb + ATT_SK + prec * 65536 + kc * 32768 + swz(r * 128 + c16 * 16), s);
    }
    CP_COMMIT();
    asm volatile("cp.async.wait_group 0;" ::: "memory");
    __syncthreads();

    // QK: S[64][256] = 3-term split. warp tile 32m x 64n
    {
        const int m_base = (wid & 1) * 32;
        const int n_base = (wid >> 1) * 64;
        float acc[2][8][4];
#pragma unroll
        for (int mt = 0; mt < 2; mt++)
#pragma unroll
            for (int nt = 0; nt < 8; nt++)
#pragma unroll
                for (int r = 0; r < 4; r++) acc[mt][nt][r] = 0.f;

        const int ap[3] = {0, 0, 1}, bp[3] = {0, 1, 0};
#pragma unroll 1
        for (int t = 0; t < 3; t++) {
            uint32_t Ab = sb + ATT_SQ + ap[t] * 16384;
            uint32_t Bb = sb + ATT_SK + bp[t] * 65536;
#pragma unroll
            for (int kc = 0; kc < 2; kc++) {
#pragma unroll
                for (int ks = 0; ks < 4; ks++) {
                    uint32_t a[2][4];
#pragma unroll
                    for (int mt = 0; mt < 2; mt++) {
                        int ra = m_base + mt * 16 + raL;
                        uint32_t ck = (uint32_t)(ks * 2 + akh) ^ (uint32_t)(ra & 7);
                        ldsm4(a[mt], Ab + kc * 8192 + (uint32_t)(ra * 128) + (ck << 4));
                    }
                    uint32_t bfr[4][4];
#pragma unroll
                    for (int nt2 = 0; nt2 < 4; nt2++) {
                        int rb = n_base + nt2 * 16 + rbL;
                        uint32_t ck = (uint32_t)(ks * 2 + bkh) ^ (uint32_t)(rb & 7);
                        ldsm4(bfr[nt2], Bb + kc * 32768 + (uint32_t)(rb * 128) + (ck << 4));
                    }
#pragma unroll
                    for (int mt = 0; mt < 2; mt++)
#pragma unroll
                        for (int nt = 0; nt < 8; nt++)
                            mma16816(acc[mt][nt], a[mt], &bfr[nt >> 1][(nt & 1) * 2]);
                }
            }
        }
        // store S * SCALE
#pragma unroll
        for (int mt = 0; mt < 2; mt++) {
            int r = m_base + mt * 16 + (lane >> 2);
#pragma unroll
            for (int nt = 0; nt < 8; nt++) {
                int c = n_base + nt * 8 + (lane & 3) * 2;
                sS[r * SST + c] = acc[mt][nt][0] * SCALE;
                sS[r * SST + c + 1] = acc[mt][nt][1] * SCALE;
                sS[(r + 8) * SST + c] = acc[mt][nt][2] * SCALE;
                sS[(r + 8) * SST + c + 1] = acc[mt][nt][3] * SCALE;
            }
        }
    }
    __syncthreads();

    // prefetch V chunks 0 (Vhi kt0) and 1 (Vlo kt0)
#pragma unroll
    for (int cch = 0; cch < 2; cch++) {
        const bf16* base = (cch ? vtlo : vthi) + pagebase;
#pragma unroll
        for (int q = 0; q < 4; q++) {
            int idx = q * 256 + tid;
            int r = idx >> 3, c16 = idx & 7;
            cp16(sb + ATT_SV + cch * 16384 + swz(r * 128 + c16 * 16),
                 base + (size_t)r * 256 + 0 * 64 + c16 * 8);
        }
        CP_COMMIT();
    }

    // softmax: warp per row
    for (int r = wid; r < 64; r += 8) {
        float v[8];
        float m = -3.4e38f;
#pragma unroll
        for (int c = 0; c < 8; c++) {
            v[c] = sS[r * SST + 32 * c + lane];
            m = fmaxf(m, v[c]);
        }
#pragma unroll
        for (int o = 16; o; o >>= 1) m = fmaxf(m, __shfl_xor_sync(0xffffffffu, m, o));
        float sum = 0.f;
#pragma unroll
        for (int c = 0; c < 8; c++) {
            v[c] = __expf(v[c] - m);
            sum += v[c];
        }
#pragma unroll
        for (int o = 16; o; o >>= 1) sum += __shfl_xor_sync(0xffffffffu, sum, o);
        float inv = 1.0f / sum;
#pragma unroll
        for (int c = 0; c < 8; c++) sS[r * SST + 32 * c + lane] = v[c] * inv;
    }
    __syncthreads();

    // P convert: S fp32 -> P hi/lo bf16 sub-tiles [prec][kc4][64][128B]
    {
        int m = tid >> 2, kcq = tid & 3;
        const float* srow = sS + m * SST + kcq * 64;
        uint32_t dh = sb + ATT_SP + kcq * 8192;
#pragma unroll
        for (int j = 0; j < 32; j++) {
            float s0 = srow[2 * j], s1 = srow[2 * j + 1];
            bf16 h0 = __float2bfloat16(s0), h1 = __float2bfloat16(s1);
            bf16 l0 = __float2bfloat16(s0 - __bfloat162float(h0));
            bf16 l1 = __float2bfloat16(s1 - __bfloat162float(h1));
            uint32_t off = swz((uint32_t)(m * 128 + 4 * j));
            *(uint32_t*)(smraw + (dh - sb) + off) = pack2(h0, h1);
            *(uint32_t*)(smraw + (dh - sb) + 32768 + off) = pack2(l0, l1);
        }
    }
    __syncthreads();

    // PV: ctx[64][128] = 3-term split, V streamed in 8 chunks.
    float acc2[2][4][4];
#pragma unroll
    for (int mt = 0; mt < 2; mt++)
#pragma unroll
        for (int nt = 0; nt < 4; nt++)
#pragma unroll
            for (int r = 0; r < 4; r++) acc2[mt][nt][r] = 0.f;

    const int m2 = (wid & 1) * 32;
    const int n2 = (wid >> 1) * 32;

#pragma unroll 1
    for (int j = 0; j < 8; j++) {
        int kt = j >> 1, vp = j & 1;
        if (j < 7) asm volatile("cp.async.wait_group 1;" ::: "memory");
        else       asm volatile("cp.async.wait_group 0;" ::: "memory");
        __syncthreads();

        uint32_t Vb = sb + ATT_SV + (j & 1) * 16384;
        int npass = vp ? 1 : 2;
#pragma unroll 1
        for (int p = 0; p < npass; p++) {
            int pp = vp ? 0 : p;  // P precision for this pass
            uint32_t Pb = sb + ATT_SP + pp * 32768 + kt * 8192;
#pragma unroll
            for (int ks = 0; ks < 4; ks++) {
                uint32_t a[2][4];
#pragma unroll
                for (int mt = 0; mt < 2; mt++) {
                    int ra = m2 + mt * 16 + raL;
                    uint32_t ck = (uint32_t)(ks * 2 + akh) ^ (uint32_t)(ra & 7);
                    ldsm4(a[mt], Pb + (uint32_t)(ra * 128) + (ck << 4));
                }
                uint32_t bfr[2][4];
#pragma unroll
                for (int nt2 = 0; nt2 < 2; nt2++) {
                    int rb = n2 + nt2 * 16 + rbL;
                    uint32_t ck = (uint32_t)(ks * 2 + bkh) ^ (uint32_t)(rb & 7);
                    ldsm4(bfr[nt2], Vb + (uint32_t)(rb * 128) + (ck << 4));
                }
#pragma unroll
                for (int mt = 0; mt < 2; mt++)
#pragma unroll
                    for (int nt = 0; nt < 4; nt++)
                        mma16816(acc2[mt][nt], a[mt], &bfr[nt >> 1][(nt & 1) * 2]);
            }
        }
        __syncthreads();

        int nchunk = j + 2;
        if (nchunk < 8) {
            int kt2 = nchunk >> 1, vp2 = nchunk & 1;
            const bf16* base = (vp2 ? vtlo : vthi) + pagebase;
#pragma unroll
            for (int q = 0; q < 4; q++) {
                int idx = q * 256 + tid;
                int r = idx >> 3, c16 = idx & 7;
                cp16(sb + ATT_SV + (j & 1) * 16384 + swz(r * 128 + c16 * 16),
                     base + (size_t)r * 256 + kt2 * 64 + c16 * 8);
            }
            CP_COMMIT();
        }
    }

    // Epilogue: ctx -> cbig [hi, hi, lo]
    const int b = x2 >> 4, head = x2 & 15;
#pragma unroll
    for (int mt = 0; mt < 2; mt++) {
        int r0 = qt * 64 + m2 + mt * 16 + (lane >> 2);
#pragma unroll
        for (int nt = 0; nt < 4; nt++) {
            int colb = h2 * 128 + n2 + nt * 8 + (lane & 3) * 2;
#pragma unroll
            for (int q = 0; q < 2; q++) {
                int r = r0 + q * 8;
                float v0 = acc2[mt][nt][q * 2], v1 = acc2[mt][nt][q * 2 + 1];
                bf16 h0 = __float2bfloat16(v0), h1 = __float2bfloat16(v1);
                bf16 l0 = __float2bfloat16(v0 - __bfloat162float(h0));
                bf16 l1 = __float2bfloat16(v1 - __bfloat162float(h1));
                uint32_t hp = pack2(h0, h1), lp = pack2(l0, l1);
                bf16* d = cbig + (size_t)(b * 4096 + head * 256 + r) * KBIG + colb;
                *(uint32_t*)d = hp;
                *(uint32_t*)(d + 2048) = hp;
                *(uint32_t*)(d + 4096) = lp;
            }
        }
    }
}

// ---------------------------------------------------------------------------
extern "C" void kernel_launch(void* const* d_in, const int* in_sizes, int n_in,
                              void* d_out, int out_size) {
    const float* hidden = (const float*)d_in[0];
    const float* Wq = (const float*)d_in[1];
    const float* bq = (const float*)d_in[2];
    const float* Wk = (const float*)d_in[3];
    const float* bk = (const float*)d_in[4];
    const float* Wv = (const float*)d_in[5];
    const float* bv = (const float*)d_in[6];
    const float* Wo = (const float*)d_in[7];
    const float* bo = (const float*)d_in[8];
    float* out = (float*)d_out;

    bf16 *hbig, *cbig, *wq, *wk, *wv, *wo;
    bf16 *qhi, *qlo, *khi, *klo, *vthi, *vtlo;
    cudaGetSymbolAddress((void**)&hbig, g_hbig);
    cudaGetSymbolAddress((void**)&cbig, g_cbig);
    cudaGetSymbolAddress((void**)&wq, g_wq);
    cudaGetSymbolAddress((void**)&wk, g_wk);
    cudaGetSymbolAddress((void**)&wv, g_wv);
    cudaGetSymbolAddress((void**)&wo, g_wo);
    cudaGetSymbolAddress((void**)&qhi, g_qhi);
    cudaGetSymbolAddress((void**)&qlo, g_qlo);
    cudaGetSymbolAddress((void**)&khi, g_khi);
    cudaGetSymbolAddress((void**)&klo, g_klo);
    cudaGetSymbolAddress((void**)&vthi, g_vthi);
    cudaGetSymbolAddress((void**)&vtlo, g_vtlo);

    cudaFuncSetAttribute(gemm_qkv, cudaFuncAttributeMaxDynamicSharedMemorySize,
                         GEMM_SMEM);
    cudaFuncSetAttribute(gemm_wo, cudaFuncAttributeMaxDynamicSharedMemorySize,
                         GEMM_SMEM);
    cudaFuncSetAttribute(attn2, cudaFuncAttributeMaxDynamicSharedMemorySize,
                         ATT_SMEM);

    make_big<<<4096, 256>>>(Wq, wq, 1);
    make_big<<<4096, 256>>>(Wk, wk, 1);
    make_big<<<4096, 256>>>(Wv, wv, 1);
    make_big<<<4096, 256>>>(Wo, wo, 1);
    make_big<<<32768, 256>>>(hidden, hbig, 0);

    gemm_qkv<<<dim3(24, 128), 256, GEMM_SMEM>>>(
        hbig, wq, wk, wv, bq, bk, bv, qhi, qlo, khi, klo, vthi, vtlo);
    attn2<<<dim3(4, 16, 64), 256, ATT_SMEM>>>(qhi, qlo, khi, klo, vthi, vtlo, cbig);
    gemm_wo<<<dim3(8, 128), 256, GEMM_SMEM>>>(cbig, wo, bo, out);
}